// round 8
// baseline (speedup 1.0000x reference)
#include <cuda_runtime.h>
#include <cuda_bf16.h>
#include <cstdint>
#include <math.h>

#define NW   2048
#define NC   8192
#define HID  768
#define FEAT 20
#define FFN  1000
#define SD   2324
#define TOPN 819
#define MSW  30
#define NP   1024        // padded FFNN width
#define N0P  3072        // GEMM0 output cols (3 x 1024)
#define KT0  48          // GEMM0 k16 tiles (768/16)
#define KT2  64          // GEMM2 k16 tiles (1024/16)

// ---------------- scratch (device globals) ----------------------------------
__device__ __align__(16) uint32_t g_docf0[2048 * 768 / 2];
__device__ __align__(16) uint32_t g_docf1[2048 * 768 / 2];
__device__ __align__(16) uint32_t g_w1f0[(N0P / 8) * KT0 * 64];
__device__ __align__(16) uint32_t g_w1f1[(N0P / 8) * KT0 * 64];
__device__ __align__(16) uint32_t g_h1f0[(NC / 16) * KT2 * 128];
__device__ __align__(16) uint32_t g_h1f1[(NC / 16) * KT2 * 128];
__device__ __align__(16) uint32_t g_w2f0[(NP / 8) * KT2 * 64];
__device__ __align__(16) uint32_t g_w2f1[(NP / 8) * KT2 * 64];
__device__ __align__(16) float g_P[(size_t)2048 * N0P];     // [P1 | P2 | P3] per word
__device__ __align__(16) float g_wd[MSW * NP];              // width contribution to h1
__device__ __align__(16) float g_b1p[NP];
__device__ __align__(16) float g_b2p[NP];
__device__ __align__(16) float g_w3p[NP];
__device__ float g_part[16][NC];
__device__ float g_scores[NC];
__device__ float g_head[NW];
__device__ float g_wsc[MSW];
__device__ int   g_top[TOPN];

// output offsets (fp32 elements)
#define O1 (NC)
#define O2 (NC + TOPN)
#define O3 (NC + 2*TOPN)
#define O4 (NC + 3*TOPN)
#define O5 (NC + 3*TOPN + TOPN*SD)

// ---------------- helpers ----------------------------------------------------
__device__ __forceinline__ void split2(float v, unsigned short& s0, unsigned short& s1) {
    __nv_bfloat16 b0 = __float2bfloat16(v);
    float r1 = v - __bfloat162float(b0);
    __nv_bfloat16 b1 = __float2bfloat16(r1);
    s0 = __bfloat16_as_ushort(b0);
    s1 = __bfloat16_as_ushort(b1);
}

#define MMA16816(c, a, b) \
    asm volatile("mma.sync.aligned.m16n8k16.row.col.f32.bf16.bf16.f32 " \
        "{%0,%1,%2,%3},{%4,%5,%6,%7},{%8,%9},{%0,%1,%2,%3};" \
        : "+f"((c)[0]), "+f"((c)[1]), "+f"((c)[2]), "+f"((c)[3]) \
        : "r"((a).x), "r"((a).y), "r"((a).z), "r"((a).w), "r"((b).x), "r"((b).y))

// ---------------- merged small prep: head | width_ffnn | pads | wd -----------
__global__ void prep_misc(const float* __restrict__ doc,
                          const float* __restrict__ hw, const float* __restrict__ hb,
                          const float* __restrict__ wpe,
                          const float* __restrict__ ww1, const float* __restrict__ wb1,
                          const float* __restrict__ ww2, const float* __restrict__ wb2,
                          const float* __restrict__ ww3, const float* __restrict__ wb3,
                          const float* __restrict__ m_b1, const float* __restrict__ m_b2,
                          const float* __restrict__ m_w3,
                          const float* __restrict__ swe, const float* __restrict__ m_w1) {
    int b = blockIdx.x, tid = threadIdx.x;
    if (b < 256) {
        int warp = b * 8 + (tid >> 5);
        int lane = tid & 31;
        const float4* dv = (const float4*)(doc + (size_t)warp * HID);
        const float4* wv = (const float4*)hw;
        float acc = 0.f;
        for (int k = lane; k < HID / 4; k += 32) {
            float4 a = dv[k], w = wv[k];
            acc += a.x*w.x + a.y*w.y + a.z*w.z + a.w*w.w;
        }
        #pragma unroll
        for (int o = 16; o; o >>= 1) acc += __shfl_xor_sync(0xffffffffu, acc, o);
        if (lane == 0) g_head[warp] = acc + hb[0];
    } else if (b < 286) {
        __shared__ float se[FEAT];
        __shared__ float h1[FFN];
        __shared__ float red[256];
        int row = b - 256;
        if (tid < FEAT) se[tid] = wpe[row * FEAT + tid];
        __syncthreads();
        for (int j = tid; j < FFN; j += 256) {
            float acc = wb1[j];
            #pragma unroll
            for (int k = 0; k < FEAT; ++k) acc = fmaf(se[k], ww1[k * FFN + j], acc);
            h1[j] = fmaxf(acc, 0.f);
        }
        __syncthreads();
        float part = 0.f;
        for (int j = tid; j < FFN; j += 256) {
            float a0 = 0.f, a1 = 0.f, a2 = 0.f, a3 = 0.f;
            int k = 0;
            for (; k + 3 < FFN; k += 4) {
                a0 = fmaf(h1[k],     ww2[(size_t)k * FFN + j], a0);
                a1 = fmaf(h1[k + 1], ww2[(size_t)(k + 1) * FFN + j], a1);
                a2 = fmaf(h1[k + 2], ww2[(size_t)(k + 2) * FFN + j], a2);
                a3 = fmaf(h1[k + 3], ww2[(size_t)(k + 3) * FFN + j], a3);
            }
            float acc = wb2[j] + ((a0 + a1) + (a2 + a3));
            part += fmaxf(acc, 0.f) * ww3[j];
        }
        red[tid] = part;
        __syncthreads();
        for (int st = 128; st; st >>= 1) {
            if (tid < st) red[tid] += red[tid + st];
            __syncthreads();
        }
        if (tid == 0) g_wsc[row] = red[0] + wb3[0];
    } else if (b < 287) {
        for (int i = tid; i < NP; i += 256) {
            g_b1p[i] = (i < FFN) ? m_b1[i] : 0.f;
            g_b2p[i] = (i < FFN) ? m_b2[i] : 0.f;
            g_w3p[i] = (i < FFN) ? m_w3[i] : 0.f;
        }
    } else {
        int i = (b - 287) * 256 + tid;
        int w = i / NP, n = i % NP;
        float acc = 0.f;
        if (n < FFN)
            #pragma unroll
            for (int f = 0; f < FEAT; ++f)
                acc = fmaf(swe[w * FEAT + f], m_w1[(size_t)(1536 + f) * FFN + n], acc);
        g_wd[i] = acc;
    }
}

// ---------------- doc -> A-fragment bf16 splits ------------------------------
__global__ void docfrag(const float* __restrict__ doc) {
    int i = blockIdx.x * blockDim.x + threadIdx.x;
    if (i >= 2048 * 384) return;
    int m = i / 384, kp = i % 384;
    int k = kp * 2;
    float v0 = doc[(size_t)m * HID + k];
    float v1 = doc[(size_t)m * HID + k + 1];
    unsigned short a0, a1, b0, b1;
    split2(v0, a0, a1);
    split2(v1, b0, b1);
    int mt = m >> 4, kt = k >> 4, r = m & 15, ck = k & 15;
    int t = ((r & 7) << 2) | ((ck >> 1) & 3);
    int reg = (r >> 3) + 2 * (ck >> 3);
    int idx = (mt * KT0 + kt) * 128 + t * 4 + reg;
    g_docf0[idx] = (uint32_t)a0 | ((uint32_t)b0 << 16);
    g_docf1[idx] = (uint32_t)a1 | ((uint32_t)b1 << 16);
}

// ---------------- W1cat + W2 -> B-fragment bf16 splits (merged) --------------
#define W1E (384 * N0P)
__global__ void wfrag_all(const float* __restrict__ w1, const float* __restrict__ w2) {
    int i = blockIdx.x * blockDim.x + threadIdx.x;
    int mode, KP, n, kp;
    if (i < W1E) { mode = 0; KP = 384; }
    else         { mode = 1; KP = 512; i -= W1E; if (i >= 512 * NP) return; }
    n = i / KP; kp = i % KP;
    int k = kp * 2;
    float v0 = 0.f, v1 = 0.f;
    if (mode == 0) {
        int blk = n >> 10, nn = n & 1023;
        if (nn < FFN) {
            int row = (blk == 0) ? k : (blk == 1) ? 768 + k : 1556 + k;
            v0 = w1[(size_t)row * FFN + nn];
            v1 = w1[(size_t)(row + 1) * FFN + nn];
        }
    } else {
        if (n < FFN && k < FFN) {
            v0 = w2[(size_t)k * FFN + n];
            v1 = (k + 1 < FFN) ? w2[(size_t)(k + 1) * FFN + n] : 0.f;
        }
    }
    unsigned short a0, a1, b0, b1;
    split2(v0, a0, a1);
    split2(v1, b0, b1);
    int KTt = mode ? KT2 : KT0;
    int idx = ((n >> 3) * KTt + (k >> 4)) * 64
            + (((n & 7) << 2) | ((k >> 1) & 3)) * 2 + ((k >> 3) & 1);
    if (mode == 0) {
        g_w1f0[idx] = (uint32_t)a0 | ((uint32_t)b0 << 16);
        g_w1f1[idx] = (uint32_t)a1 | ((uint32_t)b1 << 16);
    } else {
        g_w2f0[idx] = (uint32_t)a0 | ((uint32_t)b0 << 16);
        g_w2f1[idx] = (uint32_t)a1 | ((uint32_t)b1 << 16);
    }
}

// ---------------- fragment-layout split2 GEMM (HMMA, 3 products) -------------
// CTA: 128 rows x 64 cols; 8 warps as 2(m) x 4(n); warp tile 64x16.
template<int KT, int MODE>
__global__ void __launch_bounds__(256, 2)
frag_gemm(const uint4* __restrict__ A0, const uint4* __restrict__ A1,
          const uint2* __restrict__ B0, const uint2* __restrict__ B1,
          float* __restrict__ Cout, int Nstride) {
    int lane = threadIdx.x & 31, wid = threadIdx.x >> 5;
    int wm = wid >> 2, wn = wid & 3;
    int mtb = blockIdx.y * 8 + wm * 4;
    int ntb = blockIdx.x * 8 + wn * 2;
    float c[4][2][4];
    #pragma unroll
    for (int i = 0; i < 4; ++i)
        #pragma unroll
        for (int j = 0; j < 2; ++j)
            #pragma unroll
            for (int q = 0; q < 4; ++q) c[i][j][q] = 0.f;

    #pragma unroll 2
    for (int kt = 0; kt < KT; ++kt) {
        uint4 a0[4], a1[4];
        uint2 b0[2], b1[2];
        #pragma unroll
        for (int i = 0; i < 4; ++i) {
            int off = ((mtb + i) * KT + kt) * 32 + lane;
            a0[i] = A0[off]; a1[i] = A1[off];
        }
        #pragma unroll
        for (int j = 0; j < 2; ++j) {
            int off = ((ntb + j) * KT + kt) * 32 + lane;
            b0[j] = B0[off]; b1[j] = B1[off];
        }
        // 3 significant products: a0b0, a0b1, a1b0 (a1b1 ~2^-32, dropped)
        #pragma unroll
        for (int i = 0; i < 4; ++i)
            #pragma unroll
            for (int j = 0; j < 2; ++j) {
                MMA16816(c[i][j], a0[i], b0[j]);
                MMA16816(c[i][j], a0[i], b1[j]);
                MMA16816(c[i][j], a1[i], b0[j]);
            }
    }

    int g = lane >> 2, tg = lane & 3;
    if (MODE == 0) {
        #pragma unroll
        for (int i = 0; i < 4; ++i) {
            int m = (mtb + i) * 16 + g;
            #pragma unroll
            for (int j = 0; j < 2; ++j) {
                int n = (ntb + j) * 8 + tg * 2;
                *(float2*)&Cout[(size_t)m * Nstride + n] = make_float2(c[i][j][0], c[i][j][1]);
                *(float2*)&Cout[(size_t)(m + 8) * Nstride + n] = make_float2(c[i][j][2], c[i][j][3]);
            }
        }
    } else {
        __shared__ float sred[4][128];
        #pragma unroll
        for (int i = 0; i < 4; ++i) {
            float r0 = 0.f, r1 = 0.f;
            #pragma unroll
            for (int j = 0; j < 2; ++j) {
                int n = (ntb + j) * 8 + tg * 2;
                float ba = g_b2p[n], bb = g_b2p[n + 1];
                float wa = g_w3p[n], wb = g_w3p[n + 1];
                r0 += fmaxf(c[i][j][0] + ba, 0.f) * wa + fmaxf(c[i][j][1] + bb, 0.f) * wb;
                r1 += fmaxf(c[i][j][2] + ba, 0.f) * wa + fmaxf(c[i][j][3] + bb, 0.f) * wb;
            }
            r0 += __shfl_xor_sync(0xffffffffu, r0, 1);
            r0 += __shfl_xor_sync(0xffffffffu, r0, 2);
            r1 += __shfl_xor_sync(0xffffffffu, r1, 1);
            r1 += __shfl_xor_sync(0xffffffffu, r1, 2);
            if (tg == 0) {
                int lr = wm * 64 + i * 16 + g;
                sred[wn][lr] = r0;
                sred[wn][lr + 8] = r1;
            }
        }
        __syncthreads();
        int tid = threadIdx.x;
        if (tid < 128) {
            float s = sred[0][tid] + sred[1][tid] + sred[2][tid] + sred[3][tid];
            g_part[blockIdx.x][blockIdx.y * 128 + tid] = s;
        }
    }
}

// ---------------- candidate h1 assembly --------------------------------------
__global__ void assemble_h1(const int* __restrict__ starts, const int* __restrict__ ends) {
    int cand = blockIdx.x;
    int s = starts[cand], e = ends[cand], w = e - s;
    __shared__ float attn[32];
    int tid = threadIdx.x;
    if (tid < 32) {
        bool v = (tid <= w);
        float hv = v ? g_head[s + tid] : -INFINITY;
        float m = hv;
        #pragma unroll
        for (int o = 16; o; o >>= 1) m = fmaxf(m, __shfl_xor_sync(0xffffffffu, m, o));
        float ex = v ? expf(hv - m) : 0.f;
        float sum = ex;
        #pragma unroll
        for (int o = 16; o; o >>= 1) sum += __shfl_xor_sync(0xffffffffu, sum, o);
        attn[tid] = ex / sum;
    }
    __syncthreads();

    int n0 = tid * 4;
    float4 p1 = *(const float4*)&g_P[(size_t)s * N0P + n0];
    float4 p2 = *(const float4*)&g_P[(size_t)e * N0P + 1024 + n0];
    float4 wd = *(const float4*)&g_wd[w * NP + n0];
    float4 b1 = *(const float4*)&g_b1p[n0];
    float a0 = p1.x + p2.x + wd.x + b1.x;
    float a1 = p1.y + p2.y + wd.y + b1.y;
    float a2 = p1.z + p2.z + wd.z + b1.z;
    float a3 = p1.w + p2.w + wd.w + b1.w;
    for (int j = 0; j <= w; ++j) {
        float wt = attn[j];
        float4 p3 = *(const float4*)&g_P[(size_t)(s + j) * N0P + 2048 + n0];
        a0 = fmaf(wt, p3.x, a0); a1 = fmaf(wt, p3.y, a1);
        a2 = fmaf(wt, p3.z, a2); a3 = fmaf(wt, p3.w, a3);
    }
    a0 = fmaxf(a0, 0.f); a1 = fmaxf(a1, 0.f);
    a2 = fmaxf(a2, 0.f); a3 = fmaxf(a3, 0.f);

    unsigned short x0[4], x1[4];
    split2(a0, x0[0], x1[0]);
    split2(a1, x0[1], x1[1]);
    split2(a2, x0[2], x1[2]);
    split2(a3, x0[3], x1[3]);

    int mt = cand >> 4, r = cand & 15;
    int kt = n0 >> 4, c4 = n0 & 15;
    int t = ((r & 7) << 2) | ((c4 >> 1) & 3);
    int reg = (r >> 3) + 2 * (c4 >> 3);
    int idx = (mt * KT2 + kt) * 128 + t * 4 + reg;
    g_h1f0[idx]     = (uint32_t)x0[0] | ((uint32_t)x0[1] << 16);
    g_h1f1[idx]     = (uint32_t)x1[0] | ((uint32_t)x1[1] << 16);
    g_h1f0[idx + 4] = (uint32_t)x0[2] | ((uint32_t)x0[3] << 16);
    g_h1f1[idx + 4] = (uint32_t)x1[2] | ((uint32_t)x1[3] << 16);
}

// ---------------- final scores (also writes out[0:NC]) -----------------------
__global__ void score2(const float* __restrict__ b3,
                       const int* __restrict__ st, const int* __restrict__ en,
                       float* __restrict__ out) {
    int i = blockIdx.x * blockDim.x + threadIdx.x;
    if (i < NC) {
        float s = b3[0] + g_wsc[en[i] - st[i]];
        #pragma unroll
        for (int p = 0; p < 16; ++p) s += g_part[p][i];
        g_scores[i] = s;
        out[i] = s;
    }
}

// ---------------- NMS: sort + windowed incremental greedy --------------------
#define NMS_SMEM (NC*8 + NC*4*2 + NW*4*2 + 1024*4 + 16)

__global__ void __launch_bounds__(1024)
nms_kernel(const int* __restrict__ gstarts, const int* __restrict__ gends) {
    extern __shared__ unsigned char smraw[];
    uint64_t* keys = (uint64_t*)smraw;
    int* sSt = (int*)(keys + NC);
    int* sEn = sSt + NC;
    int* maxEnd = sEn + NC;
    int* minStart = maxEnd + NW;
    int* sel = minStart + NW;
    int* pcount = sel + 1024;
    int tid = threadIdx.x;

    for (int i = tid; i < NC; i += 1024) {
        unsigned u = __float_as_uint(g_scores[i]);
        u = (u & 0x80000000u) ? ~u : (u | 0x80000000u);
        keys[i] = ((uint64_t)(~u) << 32) | (unsigned)i;
        sSt[i] = gstarts[i];
        sEn[i] = gends[i];
    }
    for (int i = tid; i < NW; i += 1024) { maxEnd[i] = -1; minStart[i] = NW; }
    if (tid == 0) *pcount = 0;
    __syncthreads();

    for (int k = 2; k <= NC; k <<= 1)
        for (int j = k >> 1; j > 0; j >>= 1) {
            for (int i = tid; i < NC; i += 1024) {
                int ixj = i ^ j;
                if (ixj > i) {
                    bool up = (i & k) == 0;
                    uint64_t a = keys[i], b = keys[ixj];
                    if (up ? (a > b) : (a < b)) { keys[i] = b; keys[ixj] = a; }
                }
            }
            __syncthreads();
        }

    if (tid < 32) {
        int lane = tid;
        int count = 0;
        for (int base = 0; base < NC && count < TOPN; base += 32) {
            __syncwarp();
            int idx = (int)(keys[base + lane] & 0xffffffffu);
            int s = sSt[idx], e = sEn[idx], w = e - s;
            int myME = maxEnd[s];
            bool flag = (myME != e);
            for (int off = 0; off <= w && flag; ++off) {
                if (off > 0 && maxEnd[s + off] > e) flag = false;
                if (off < w && minStart[s + off] < s) flag = false;
            }
            unsigned ok = __ballot_sync(0xffffffffu, flag);
            while (ok) {
                int first = __ffs(ok) - 1;
                int s1 = __shfl_sync(0xffffffffu, s, first);
                int e1 = __shfl_sync(0xffffffffu, e, first);
                int idx1 = __shfl_sync(0xffffffffu, idx, first);
                if (lane == 0) {
                    sel[count] = idx1;
                    if (e1 > maxEnd[s1]) maxEnd[s1] = e1;
                    if (s1 < minStart[e1]) minStart[e1] = s1;
                }
                count++;
                if (count == TOPN) break;
                if (lane <= first) flag = false;
                else if (flag) {
                    if (s == s1 && e1 > myME) myME = e1;
                    if (myME == e) flag = false;
                    if ((s < s1 && s1 <= e && e1 > e) ||
                        (s1 < s && e1 >= s && e1 < e)) flag = false;
                }
                ok = __ballot_sync(0xffffffffu, flag);
            }
        }
        if (lane == 0) *pcount = count;
    }
    __syncthreads();
    int count = *pcount;

    {
        uint64_t k;
        if (tid < count) {
            int idx = sel[tid];
            uint64_t pk = (uint64_t)(sSt[idx] * NW + sEn[idx]);
            k = (pk << 24) | ((uint64_t)tid << 14) | (uint64_t)idx;
        } else k = ~0ull;
        keys[tid] = k;
    }
    __syncthreads();
    for (int k = 2; k <= 1024; k <<= 1)
        for (int j = k >> 1; j > 0; j >>= 1) {
            int i = tid, ixj = i ^ j;
            if (ixj > i) {
                bool up = (i & k) == 0;
                uint64_t a = keys[i], b = keys[ixj];
                if (up ? (a > b) : (a < b)) { keys[i] = b; keys[ixj] = a; }
            }
            __syncthreads();
        }
    if (tid < TOPN) {
        uint64_t kt = (tid < count) ? keys[tid] : keys[0];
        g_top[tid] = (int)(kt & 0x3FFFull);
    }
}

// ---------------- outputs: recompute top-span embeddings ---------------------
__global__ void out_top(float* __restrict__ out,
                        const float* __restrict__ doc,
                        const float* __restrict__ swe,
                        const int* __restrict__ starts, const int* __restrict__ ends) {
    int r = blockIdx.x;
    int idx = g_top[r];
    int s = starts[idx], e = ends[idx], w = e - s;
    __shared__ float attn[32];
    int tid = threadIdx.x;
    if (tid < 32) {
        bool v = (tid <= w);
        float hv = v ? g_head[s + tid] : -INFINITY;
        float m = hv;
        #pragma unroll
        for (int o = 16; o; o >>= 1) m = fmaxf(m, __shfl_xor_sync(0xffffffffu, m, o));
        float ex = v ? expf(hv - m) : 0.f;
        float sum = ex;
        #pragma unroll
        for (int o = 16; o; o >>= 1) sum += __shfl_xor_sync(0xffffffffu, sum, o);
        attn[tid] = ex / sum;
    }
    if (tid == 0) {
        out[O1 + r] = (float)idx;
        out[O2 + r] = (float)s;
        out[O3 + r] = (float)e;
        out[O5 + r] = g_scores[idx];
    }
    __syncthreads();
    float* dst = out + O4 + (size_t)r * SD;
    const float4* dv = (const float4*)doc;
    if (tid < HID / 4) {
        int h4 = tid;
        float4 st4 = dv[(size_t)s * 192 + h4];
        float4 en4 = dv[(size_t)e * 192 + h4];
        float4 a = make_float4(0.f, 0.f, 0.f, 0.f);
        for (int j = 0; j <= w; ++j) {
            float wt = attn[j];
            float4 vv = dv[(size_t)(s + j) * 192 + h4];
            a.x = fmaf(wt, vv.x, a.x); a.y = fmaf(wt, vv.y, a.y);
            a.z = fmaf(wt, vv.z, a.z); a.w = fmaf(wt, vv.w, a.w);
        }
        int h = h4 * 4;
        dst[h + 0] = st4.x; dst[h + 1] = st4.y; dst[h + 2] = st4.z; dst[h + 3] = st4.w;
        dst[HID + h + 0] = en4.x; dst[HID + h + 1] = en4.y;
        dst[HID + h + 2] = en4.z; dst[HID + h + 3] = en4.w;
        int ha = 2 * HID + FEAT + h;
        dst[ha + 0] = a.x; dst[ha + 1] = a.y; dst[ha + 2] = a.z; dst[ha + 3] = a.w;
    }
    if (tid >= 224 && tid < 224 + FEAT)
        dst[2 * HID + (tid - 224)] = swe[w * FEAT + (tid - 224)];
}

// ---------------- launch ------------------------------------------------------
extern "C" void kernel_launch(void* const* d_in, const int* in_sizes, int n_in,
                              void* d_out, int out_size) {
    const float* doc    = (const float*)d_in[0];
    const float* swe    = (const float*)d_in[1];
    const float* head_w = (const float*)d_in[2];
    const float* head_b = (const float*)d_in[3];
    const float* m_w1   = (const float*)d_in[4];
    const float* m_b1   = (const float*)d_in[5];
    const float* m_w2   = (const float*)d_in[6];
    const float* m_b2   = (const float*)d_in[7];
    const float* m_w3   = (const float*)d_in[8];
    const float* m_b3   = (const float*)d_in[9];
    const float* wpe    = (const float*)d_in[10];
    const float* w_w1   = (const float*)d_in[11];
    const float* w_b1   = (const float*)d_in[12];
    const float* w_w2   = (const float*)d_in[13];
    const float* w_b2   = (const float*)d_in[14];
    const float* w_w3   = (const float*)d_in[15];
    const float* w_b3   = (const float*)d_in[16];
    const int*   starts = (const int*)d_in[17];
    const int*   ends   = (const int*)d_in[18];
    float* out = (float*)d_out;

    void *df0, *df1, *w1f0, *w1f1, *h1f0, *h1f1, *w2f0, *w2f1, *pP;
    cudaGetSymbolAddress(&df0, g_docf0);
    cudaGetSymbolAddress(&df1, g_docf1);
    cudaGetSymbolAddress(&w1f0, g_w1f0);
    cudaGetSymbolAddress(&w1f1, g_w1f1);
    cudaGetSymbolAddress(&h1f0, g_h1f0);
    cudaGetSymbolAddress(&h1f1, g_h1f1);
    cudaGetSymbolAddress(&w2f0, g_w2f0);
    cudaGetSymbolAddress(&w2f1, g_w2f1);
    cudaGetSymbolAddress(&pP, g_P);

    cudaFuncSetAttribute(nms_kernel, cudaFuncAttributeMaxDynamicSharedMemorySize, NMS_SMEM);

    // 1
    docfrag<<<(2048 * 384 + 255) / 256, 256>>>(doc);
    // 2
    wfrag_all<<<(W1E + 512 * NP + 255) / 256, 256>>>(m_w1, m_w2);
    // 3
    prep_misc<<<287 + 120, 256>>>(doc, head_w, head_b, wpe,
                                  w_w1, w_b1, w_w2, w_b2, w_w3, w_b3,
                                  m_b1, m_b2, m_w3, swe, m_w1);
    // 4: GEMM0 doc @ W1cat
    frag_gemm<KT0, 0><<<dim3(N0P / 64, 2048 / 128), 256>>>(
        (const uint4*)df0, (const uint4*)df1,
        (const uint2*)w1f0, (const uint2*)w1f1,
        (float*)pP, N0P);
    // 5
    assemble_h1<<<NC, 256>>>(starts, ends);
    // 6: GEMM2 (profiled launch under -s 5 -c 1)
    frag_gemm<KT2, 1><<<dim3(NP / 64, NC / 128), 256>>>(
        (const uint4*)h1f0, (const uint4*)h1f1,
        (const uint2*)w2f0, (const uint2*)w2f1,
        (float*)pP, NP);
    // 7+
    score2<<<(NC + 255) / 256, 256>>>(m_b3, starts, ends, out);
    nms_kernel<<<1, 1024, NMS_SMEM>>>(starts, ends);
    out_top<<<TOPN, 256>>>(out, doc, swe, starts, ends);
}

// round 11
// speedup vs baseline: 1.1560x; 1.1560x over previous
#include <cuda_runtime.h>
#include <cuda_bf16.h>
#include <cstdint>
#include <math.h>

#define NW   2048
#define NC   8192
#define HID  768
#define FEAT 20
#define FFN  1000
#define SD   2324
#define TOPN 819
#define MSW  30
#define NP   1024        // padded FFNN width
#define N0P  3072        // GEMM0 output cols (3 x 1024)
#define KT0  48          // GEMM0 k16 tiles (768/16)
#define KT2  64          // GEMM2 k16 tiles (1024/16)

// ---------------- scratch (device globals) ----------------------------------
__device__ __align__(16) uint32_t g_docf0[2048 * 768 / 2];
__device__ __align__(16) uint32_t g_docf1[2048 * 768 / 2];
__device__ __align__(16) uint32_t g_w1f0[(N0P / 8) * KT0 * 64];
__device__ __align__(16) uint32_t g_w1f1[(N0P / 8) * KT0 * 64];
__device__ __align__(16) uint32_t g_h1f0[(NC / 16) * KT2 * 128];
__device__ __align__(16) uint32_t g_h1f1[(NC / 16) * KT2 * 128];
__device__ __align__(16) uint32_t g_w2f0[(NP / 8) * KT2 * 64];
__device__ __align__(16) uint32_t g_w2f1[(NP / 8) * KT2 * 64];
__device__ __align__(16) float g_P[(size_t)2048 * N0P];     // [P1 | P2 | P3] per word
__device__ __align__(16) float g_wd[MSW * NP];
__device__ __align__(16) float g_b1p[NP];
__device__ __align__(16) float g_b2p[NP];
__device__ __align__(16) float g_w3p[NP];
__device__ float g_part[8][NC];
__device__ float g_scores[NC];
__device__ float g_head[NW];
__device__ float g_wsc[MSW];
__device__ int   g_top[TOPN];

// output offsets (fp32 elements)
#define O1 (NC)
#define O2 (NC + TOPN)
#define O3 (NC + 2*TOPN)
#define O4 (NC + 3*TOPN)
#define O5 (NC + 3*TOPN + TOPN*SD)

// ---------------- helpers ----------------------------------------------------
__device__ __forceinline__ void split2(float v, unsigned short& s0, unsigned short& s1) {
    __nv_bfloat16 b0 = __float2bfloat16(v);
    float r1 = v - __bfloat162float(b0);
    __nv_bfloat16 b1 = __float2bfloat16(r1);
    s0 = __bfloat16_as_ushort(b0);
    s1 = __bfloat16_as_ushort(b1);
}

#define MMA16816(c, a, b) \
    asm volatile("mma.sync.aligned.m16n8k16.row.col.f32.bf16.bf16.f32 " \
        "{%0,%1,%2,%3},{%4,%5,%6,%7},{%8,%9},{%0,%1,%2,%3};" \
        : "+f"((c)[0]), "+f"((c)[1]), "+f"((c)[2]), "+f"((c)[3]) \
        : "r"((a).x), "r"((a).y), "r"((a).z), "r"((a).w), "r"((b).x), "r"((b).y))

// ---------------- merged small prep: head | width_ffnn | pads | wd -----------
__global__ void prep_misc(const float* __restrict__ doc,
                          const float* __restrict__ hw, const float* __restrict__ hb,
                          const float* __restrict__ wpe,
                          const float* __restrict__ ww1, const float* __restrict__ wb1,
                          const float* __restrict__ ww2, const float* __restrict__ wb2,
                          const float* __restrict__ ww3, const float* __restrict__ wb3,
                          const float* __restrict__ m_b1, const float* __restrict__ m_b2,
                          const float* __restrict__ m_w3,
                          const float* __restrict__ swe, const float* __restrict__ m_w1) {
    int b = blockIdx.x, tid = threadIdx.x;
    if (b < 256) {
        int warp = b * 8 + (tid >> 5);
        int lane = tid & 31;
        const float4* dv = (const float4*)(doc + (size_t)warp * HID);
        const float4* wv = (const float4*)hw;
        float acc = 0.f;
        for (int k = lane; k < HID / 4; k += 32) {
            float4 a = dv[k], w = wv[k];
            acc += a.x*w.x + a.y*w.y + a.z*w.z + a.w*w.w;
        }
        #pragma unroll
        for (int o = 16; o; o >>= 1) acc += __shfl_xor_sync(0xffffffffu, acc, o);
        if (lane == 0) g_head[warp] = acc + hb[0];
    } else if (b < 286) {
        __shared__ float se[FEAT];
        __shared__ float h1[FFN];
        __shared__ float red[256];
        int row = b - 256;
        if (tid < FEAT) se[tid] = wpe[row * FEAT + tid];
        __syncthreads();
        for (int j = tid; j < FFN; j += 256) {
            float acc = wb1[j];
            #pragma unroll
            for (int k = 0; k < FEAT; ++k) acc = fmaf(se[k], ww1[k * FFN + j], acc);
            h1[j] = fmaxf(acc, 0.f);
        }
        __syncthreads();
        float part = 0.f;
        for (int j = tid; j < FFN; j += 256) {
            float a0 = 0.f, a1 = 0.f, a2 = 0.f, a3 = 0.f;
            int k = 0;
            for (; k + 3 < FFN; k += 4) {
                a0 = fmaf(h1[k],     ww2[(size_t)k * FFN + j], a0);
                a1 = fmaf(h1[k + 1], ww2[(size_t)(k + 1) * FFN + j], a1);
                a2 = fmaf(h1[k + 2], ww2[(size_t)(k + 2) * FFN + j], a2);
                a3 = fmaf(h1[k + 3], ww2[(size_t)(k + 3) * FFN + j], a3);
            }
            float acc = wb2[j] + ((a0 + a1) + (a2 + a3));
            part += fmaxf(acc, 0.f) * ww3[j];
        }
        red[tid] = part;
        __syncthreads();
        for (int st = 128; st; st >>= 1) {
            if (tid < st) red[tid] += red[tid + st];
            __syncthreads();
        }
        if (tid == 0) g_wsc[row] = red[0] + wb3[0];
    } else if (b < 287) {
        for (int i = tid; i < NP; i += 256) {
            g_b1p[i] = (i < FFN) ? m_b1[i] : 0.f;
            g_b2p[i] = (i < FFN) ? m_b2[i] : 0.f;
            g_w3p[i] = (i < FFN) ? m_w3[i] : 0.f;
        }
    } else {
        int i = (b - 287) * 256 + tid;
        int w = i / NP, n = i % NP;
        float acc = 0.f;
        if (n < FFN)
            #pragma unroll
            for (int f = 0; f < FEAT; ++f)
                acc = fmaf(swe[w * FEAT + f], m_w1[(size_t)(1536 + f) * FFN + n], acc);
        g_wd[i] = acc;
    }
}

// ---------------- doc -> A-fragment bf16 splits ------------------------------
__global__ void docfrag(const float* __restrict__ doc) {
    int i = blockIdx.x * blockDim.x + threadIdx.x;
    if (i >= 2048 * 384) return;
    int m = i / 384, kp = i % 384;
    int k = kp * 2;
    float v0 = doc[(size_t)m * HID + k];
    float v1 = doc[(size_t)m * HID + k + 1];
    unsigned short a0, a1, b0, b1;
    split2(v0, a0, a1);
    split2(v1, b0, b1);
    int mt = m >> 4, kt = k >> 4, r = m & 15, ck = k & 15;
    int t = ((r & 7) << 2) | ((ck >> 1) & 3);
    int reg = (r >> 3) + 2 * (ck >> 3);
    int idx = (mt * KT0 + kt) * 128 + t * 4 + reg;
    g_docf0[idx] = (uint32_t)a0 | ((uint32_t)b0 << 16);
    g_docf1[idx] = (uint32_t)a1 | ((uint32_t)b1 << 16);
}

// ---------------- W1cat + W2 -> B-fragments, kt-PAIRED layout ----------------
// B idx32 = ((n>>3)*(KT/2) + (k>>5))*128 + t*4 + q*2 + r,
//   t = ((n&7)<<2)|((k>>1)&3), q = (k>>4)&1 (kt parity), r = (k>>3)&1.
// -> one uint4 per (lane, kt-pair): {kt0.r0, kt0.r1, kt1.r0, kt1.r1}
#define W1E (384 * N0P)
__global__ void wfrag_all(const float* __restrict__ w1, const float* __restrict__ w2) {
    int i = blockIdx.x * blockDim.x + threadIdx.x;
    int mode, KP, n, kp;
    if (i < W1E) { mode = 0; KP = 384; }
    else         { mode = 1; KP = 512; i -= W1E; if (i >= 512 * NP) return; }
    n = i / KP; kp = i % KP;
    int k = kp * 2;
    float v0 = 0.f, v1 = 0.f;
    if (mode == 0) {
        int blk = n >> 10, nn = n & 1023;
        if (nn < FFN) {
            int row = (blk == 0) ? k : (blk == 1) ? 768 + k : 1556 + k;
            v0 = w1[(size_t)row * FFN + nn];
            v1 = w1[(size_t)(row + 1) * FFN + nn];
        }
    } else {
        if (n < FFN && k < FFN) {
            v0 = w2[(size_t)k * FFN + n];
            v1 = (k + 1 < FFN) ? w2[(size_t)(k + 1) * FFN + n] : 0.f;
        }
    }
    unsigned short a0, a1, b0, b1;
    split2(v0, a0, a1);
    split2(v1, b0, b1);
    int KTt = mode ? KT2 : KT0;
    int t = ((n & 7) << 2) | ((k >> 1) & 3);
    int idx = ((n >> 3) * (KTt >> 1) + (k >> 5)) * 128
            + t * 4 + (((k >> 4) & 1) << 1) + ((k >> 3) & 1);
    if (mode == 0) {
        g_w1f0[idx] = (uint32_t)a0 | ((uint32_t)b0 << 16);
        g_w1f1[idx] = (uint32_t)a1 | ((uint32_t)b1 << 16);
    } else {
        g_w2f0[idx] = (uint32_t)a0 | ((uint32_t)b0 << 16);
        g_w2f1[idx] = (uint32_t)a1 | ((uint32_t)b1 << 16);
    }
}

// ---------------- fragment GEMM: warp tile 64x32, kt-paired B ----------------
// CTA: 128 rows x 128 cols; 8 warps as 2(m) x 4(n); 3 products a0b0,a0b1,a1b0.
template<int KT, int MODE>
__global__ void __launch_bounds__(256, 1)
frag_gemm(const uint4* __restrict__ A0, const uint4* __restrict__ A1,
          const uint4* __restrict__ B0, const uint4* __restrict__ B1,
          float* __restrict__ Cout, int Nstride) {
    int lane = threadIdx.x & 31, wid = threadIdx.x >> 5;
    int wm = wid >> 2, wn = wid & 3;
    int mtb = blockIdx.y * 8 + wm * 4;      // 16-row tiles
    int ntb = blockIdx.x * 16 + wn * 4;     // 8-col tiles
    float c[4][4][4];
    #pragma unroll
    for (int i = 0; i < 4; ++i)
        #pragma unroll
        for (int j = 0; j < 4; ++j)
            #pragma unroll
            for (int q = 0; q < 4; ++q) c[i][j][q] = 0.f;

    for (int p = 0; p < KT / 2; ++p) {
        uint4 bp0[4], bp1[4];
        #pragma unroll
        for (int j = 0; j < 4; ++j) {
            int off = ((ntb + j) * (KT / 2) + p) * 32 + lane;
            bp0[j] = B0[off]; bp1[j] = B1[off];
        }
        #pragma unroll
        for (int q = 0; q < 2; ++q) {
            uint4 a0[4], a1[4];
            #pragma unroll
            for (int i = 0; i < 4; ++i) {
                int off = ((mtb + i) * KT + 2 * p + q) * 32 + lane;
                a0[i] = A0[off]; a1[i] = A1[off];
            }
            #pragma unroll
            for (int i = 0; i < 4; ++i)
                #pragma unroll
                for (int j = 0; j < 4; ++j) {
                    uint2 b0 = q ? make_uint2(bp0[j].z, bp0[j].w)
                                 : make_uint2(bp0[j].x, bp0[j].y);
                    uint2 b1 = q ? make_uint2(bp1[j].z, bp1[j].w)
                                 : make_uint2(bp1[j].x, bp1[j].y);
                    MMA16816(c[i][j], a0[i], b0);
                    MMA16816(c[i][j], a0[i], b1);
                    MMA16816(c[i][j], a1[i], b0);
                }
        }
    }

    int g = lane >> 2, tg = lane & 3;
    if (MODE == 0) {
        #pragma unroll
        for (int i = 0; i < 4; ++i) {
            int m = (mtb + i) * 16 + g;
            #pragma unroll
            for (int j = 0; j < 4; ++j) {
                int n = (ntb + j) * 8 + tg * 2;
                *(float2*)&Cout[(size_t)m * Nstride + n] = make_float2(c[i][j][0], c[i][j][1]);
                *(float2*)&Cout[(size_t)(m + 8) * Nstride + n] = make_float2(c[i][j][2], c[i][j][3]);
            }
        }
    } else {
        __shared__ float sred[4][128];
        #pragma unroll
        for (int i = 0; i < 4; ++i) {
            float r0 = 0.f, r1 = 0.f;
            #pragma unroll
            for (int j = 0; j < 4; ++j) {
                int n = (ntb + j) * 8 + tg * 2;
                float ba = g_b2p[n], bb = g_b2p[n + 1];
                float wa = g_w3p[n], wb = g_w3p[n + 1];
                r0 += fmaxf(c[i][j][0] + ba, 0.f) * wa + fmaxf(c[i][j][1] + bb, 0.f) * wb;
                r1 += fmaxf(c[i][j][2] + ba, 0.f) * wa + fmaxf(c[i][j][3] + bb, 0.f) * wb;
            }
            r0 += __shfl_xor_sync(0xffffffffu, r0, 1);
            r0 += __shfl_xor_sync(0xffffffffu, r0, 2);
            r1 += __shfl_xor_sync(0xffffffffu, r1, 1);
            r1 += __shfl_xor_sync(0xffffffffu, r1, 2);
            if (tg == 0) {
                int lr = wm * 64 + i * 16 + g;
                sred[wn][lr] = r0;
                sred[wn][lr + 8] = r1;
            }
        }
        __syncthreads();
        int tid = threadIdx.x;
        if (tid < 128) {
            float s = sred[0][tid] + sred[1][tid] + sred[2][tid] + sred[3][tid];
            g_part[blockIdx.x][blockIdx.y * 128 + tid] = s;
        }
    }
}

// ---------------- candidate h1 assembly --------------------------------------
__global__ void assemble_h1(const int* __restrict__ starts, const int* __restrict__ ends) {
    int cand = blockIdx.x;
    int s = starts[cand], e = ends[cand], w = e - s;
    __shared__ float attn[32];
    int tid = threadIdx.x;
    if (tid < 32) {
        bool v = (tid <= w);
        float hv = v ? g_head[s + tid] : -INFINITY;
        float m = hv;
        #pragma unroll
        for (int o = 16; o; o >>= 1) m = fmaxf(m, __shfl_xor_sync(0xffffffffu, m, o));
        float ex = v ? expf(hv - m) : 0.f;
        float sum = ex;
        #pragma unroll
        for (int o = 16; o; o >>= 1) sum += __shfl_xor_sync(0xffffffffu, sum, o);
        attn[tid] = ex / sum;
    }
    __syncthreads();

    int n0 = tid * 4;
    float4 p1 = *(const float4*)&g_P[(size_t)s * N0P + n0];
    float4 p2 = *(const float4*)&g_P[(size_t)e * N0P + 1024 + n0];
    float4 wd = *(const float4*)&g_wd[w * NP + n0];
    float4 b1 = *(const float4*)&g_b1p[n0];
    float a0 = p1.x + p2.x + wd.x + b1.x;
    float a1 = p1.y + p2.y + wd.y + b1.y;
    float a2 = p1.z + p2.z + wd.z + b1.z;
    float a3 = p1.w + p2.w + wd.w + b1.w;
    for (int j = 0; j <= w; ++j) {
        float wt = attn[j];
        float4 p3 = *(const float4*)&g_P[(size_t)(s + j) * N0P + 2048 + n0];
        a0 = fmaf(wt, p3.x, a0); a1 = fmaf(wt, p3.y, a1);
        a2 = fmaf(wt, p3.z, a2); a3 = fmaf(wt, p3.w, a3);
    }
    a0 = fmaxf(a0, 0.f); a1 = fmaxf(a1, 0.f);
    a2 = fmaxf(a2, 0.f); a3 = fmaxf(a3, 0.f);

    unsigned short x0[4], x1[4];
    split2(a0, x0[0], x1[0]);
    split2(a1, x0[1], x1[1]);
    split2(a2, x0[2], x1[2]);
    split2(a3, x0[3], x1[3]);

    int mt = cand >> 4, r = cand & 15;
    int kt = n0 >> 4, c4 = n0 & 15;
    int t = ((r & 7) << 2) | ((c4 >> 1) & 3);
    int reg = (r >> 3) + 2 * (c4 >> 3);
    int idx = (mt * KT2 + kt) * 128 + t * 4 + reg;
    g_h1f0[idx]     = (uint32_t)x0[0] | ((uint32_t)x0[1] << 16);
    g_h1f1[idx]     = (uint32_t)x1[0] | ((uint32_t)x1[1] << 16);
    g_h1f0[idx + 4] = (uint32_t)x0[2] | ((uint32_t)x0[3] << 16);
    g_h1f1[idx + 4] = (uint32_t)x1[2] | ((uint32_t)x1[3] << 16);
}

// ---------------- final scores (also writes out[0:NC]) -----------------------
__global__ void score2(const float* __restrict__ b3,
                       const int* __restrict__ st, const int* __restrict__ en,
                       float* __restrict__ out) {
    int i = blockIdx.x * blockDim.x + threadIdx.x;
    if (i < NC) {
        float s = b3[0] + g_wsc[en[i] - st[i]];
        #pragma unroll
        for (int p = 0; p < 8; ++p) s += g_part[p][i];
        g_scores[i] = s;
        out[i] = s;
    }
}

// ---------------- NMS: sort + parallel-validate windowed greedy --------------
#define NMS_SMEM (NC*8 + NC*4*2 + NW*4*2 + 1024*4 + 16 + 1024)

__global__ void __launch_bounds__(1024)
nms_kernel(const int* __restrict__ gstarts, const int* __restrict__ gends) {
    extern __shared__ unsigned char smraw[];
    uint64_t* keys = (uint64_t*)smraw;
    int* sSt = (int*)(keys + NC);
    int* sEn = sSt + NC;
    int* maxEnd = sEn + NC;
    int* minStart = maxEnd + NW;
    int* sel = minStart + NW;
    int* pcount = sel + 1024;
    int* vS   = pcount + 1;
    int* vE   = vS + 32;
    int* vIdx = vE + 32;
    int* vME  = vIdx + 32;
    int* vFlag = vME + 32;
    int tid = threadIdx.x;
    int wi = tid >> 5, lanev = tid & 31;

    for (int i = tid; i < NC; i += 1024) {
        unsigned u = __float_as_uint(g_scores[i]);
        u = (u & 0x80000000u) ? ~u : (u | 0x80000000u);
        keys[i] = ((uint64_t)(~u) << 32) | (unsigned)i;
        sSt[i] = gstarts[i];
        sEn[i] = gends[i];
    }
    for (int i = tid; i < NW; i += 1024) { maxEnd[i] = -1; minStart[i] = NW; }
    if (tid == 0) *pcount = 0;
    __syncthreads();

    for (int k = 2; k <= NC; k <<= 1)
        for (int j = k >> 1; j > 0; j >>= 1) {
            for (int i = tid; i < NC; i += 1024) {
                int ixj = i ^ j;
                if (ixj > i) {
                    bool up = (i & k) == 0;
                    uint64_t a = keys[i], b = keys[ixj];
                    if (up ? (a > b) : (a < b)) { keys[i] = b; keys[ixj] = a; }
                }
            }
            __syncthreads();
        }

    // windowed greedy: 32 warps validate 32 candidates in parallel,
    // warp 0 does the exact sequential-equivalent incremental commit.
    for (int base = 0; base < NC; base += 32) {
        __syncthreads();
        if (*pcount >= TOPN) break;
        {   // parallel validation: warp wi -> candidate base+wi, lane -> offset
            int idx = (int)(keys[base + wi] & 0xffffffffu);
            int s = sSt[idx], e = sEn[idx], w = e - s;
            bool bad = false;
            if (lanev > 0 && lanev <= w && maxEnd[s + lanev] > e) bad = true;
            if (lanev < w && minStart[s + lanev] < s) bad = true;
            unsigned badm = __ballot_sync(0xffffffffu, bad);
            if (lanev == 0) {
                int myME = maxEnd[s];
                vS[wi] = s; vE[wi] = e; vIdx[wi] = idx; vME[wi] = myME;
                vFlag[wi] = (badm == 0 && myME != e) ? 1 : 0;
            }
        }
        __syncthreads();
        if (tid < 32) {
            int lane = tid;
            int count = *pcount;
            int s = vS[lane], e = vE[lane], idx = vIdx[lane], myME = vME[lane];
            bool flag = vFlag[lane] != 0;
            unsigned ok = __ballot_sync(0xffffffffu, flag);
            while (ok) {
                int first = __ffs(ok) - 1;
                int s1 = __shfl_sync(0xffffffffu, s, first);
                int e1 = __shfl_sync(0xffffffffu, e, first);
                int idx1 = __shfl_sync(0xffffffffu, idx, first);
                if (lane == 0) {
                    sel[count] = idx1;
                    if (e1 > maxEnd[s1]) maxEnd[s1] = e1;
                    if (s1 < minStart[e1]) minStart[e1] = s1;
                }
                count++;
                if (count == TOPN) break;
                if (lane <= first) flag = false;
                else if (flag) {
                    if (s == s1 && e1 > myME) myME = e1;
                    if (myME == e) flag = false;
                    if ((s < s1 && s1 <= e && e1 > e) ||
                        (s1 < s && e1 >= s && e1 < e)) flag = false;
                }
                ok = __ballot_sync(0xffffffffu, flag);
            }
            if (lane == 0) *pcount = count;
        }
    }
    __syncthreads();
    int count = *pcount;

    {
        uint64_t k;
        if (tid < count) {
            int idx = sel[tid];
            uint64_t pk = (uint64_t)(sSt[idx] * NW + sEn[idx]);
            k = (pk << 24) | ((uint64_t)tid << 14) | (uint64_t)idx;
        } else k = ~0ull;
        keys[tid] = k;
    }
    __syncthreads();
    for (int k = 2; k <= 1024; k <<= 1)
        for (int j = k >> 1; j > 0; j >>= 1) {
            int i = tid, ixj = i ^ j;
            if (ixj > i) {
                bool up = (i & k) == 0;
                uint64_t a = keys[i], b = keys[ixj];
                if (up ? (a > b) : (a < b)) { keys[i] = b; keys[ixj] = a; }
            }
            __syncthreads();
        }
    if (tid < TOPN) {
        uint64_t kt = (tid < count) ? keys[tid] : keys[0];
        g_top[tid] = (int)(kt & 0x3FFFull);
    }
}

// ---------------- outputs: recompute top-span embeddings ---------------------
__global__ void out_top(float* __restrict__ out,
                        const float* __restrict__ doc,
                        const float* __restrict__ swe,
                        const int* __restrict__ starts, const int* __restrict__ ends) {
    int r = blockIdx.x;
    int idx = g_top[r];
    int s = starts[idx], e = ends[idx], w = e - s;
    __shared__ float attn[32];
    int tid = threadIdx.x;
    if (tid < 32) {
        bool v = (tid <= w);
        float hv = v ? g_head[s + tid] : -INFINITY;
        float m = hv;
        #pragma unroll
        for (int o = 16; o; o >>= 1) m = fmaxf(m, __shfl_xor_sync(0xffffffffu, m, o));
        float ex = v ? expf(hv - m) : 0.f;
        float sum = ex;
        #pragma unroll
        for (int o = 16; o; o >>= 1) sum += __shfl_xor_sync(0xffffffffu, sum, o);
        attn[tid] = ex / sum;
    }
    if (tid == 0) {
        out[O1 + r] = (float)idx;
        out[O2 + r] = (float)s;
        out[O3 + r] = (float)e;
        out[O5 + r] = g_scores[idx];
    }
    __syncthreads();
    float* dst = out + O4 + (size_t)r * SD;
    const float4* dv = (const float4*)doc;
    if (tid < HID / 4) {
        int h4 = tid;
        float4 st4 = dv[(size_t)s * 192 + h4];
        float4 en4 = dv[(size_t)e * 192 + h4];
        float4 a = make_float4(0.f, 0.f, 0.f, 0.f);
        for (int j = 0; j <= w; ++j) {
            float wt = attn[j];
            float4 vv = dv[(size_t)(s + j) * 192 + h4];
            a.x = fmaf(wt, vv.x, a.x); a.y = fmaf(wt, vv.y, a.y);
            a.z = fmaf(wt, vv.z, a.z); a.w = fmaf(wt, vv.w, a.w);
        }
        int h = h4 * 4;
        dst[h + 0] = st4.x; dst[h + 1] = st4.y; dst[h + 2] = st4.z; dst[h + 3] = st4.w;
        dst[HID + h + 0] = en4.x; dst[HID + h + 1] = en4.y;
        dst[HID + h + 2] = en4.z; dst[HID + h + 3] = en4.w;
        int ha = 2 * HID + FEAT + h;
        dst[ha + 0] = a.x; dst[ha + 1] = a.y; dst[ha + 2] = a.z; dst[ha + 3] = a.w;
    }
    if (tid >= 224 && tid < 224 + FEAT)
        dst[2 * HID + (tid - 224)] = swe[w * FEAT + (tid - 224)];
}

// ---------------- launch ------------------------------------------------------
extern "C" void kernel_launch(void* const* d_in, const int* in_sizes, int n_in,
                              void* d_out, int out_size) {
    const float* doc    = (const float*)d_in[0];
    const float* swe    = (const float*)d_in[1];
    const float* head_w = (const float*)d_in[2];
    const float* head_b = (const float*)d_in[3];
    const float* m_w1   = (const float*)d_in[4];
    const float* m_b1   = (const float*)d_in[5];
    const float* m_w2   = (const float*)d_in[6];
    const float* m_b2   = (const float*)d_in[7];
    const float* m_w3   = (const float*)d_in[8];
    const float* m_b3   = (const float*)d_in[9];
    const float* wpe    = (const float*)d_in[10];
    const float* w_w1   = (const float*)d_in[11];
    const float* w_b1   = (const float*)d_in[12];
    const float* w_w2   = (const float*)d_in[13];
    const float* w_b2   = (const float*)d_in[14];
    const float* w_w3   = (const float*)d_in[15];
    const float* w_b3   = (const float*)d_in[16];
    const int*   starts = (const int*)d_in[17];
    const int*   ends   = (const int*)d_in[18];
    float* out = (float*)d_out;

    void *df0, *df1, *w1f0, *w1f1, *h1f0, *h1f1, *w2f0, *w2f1, *pP;
    cudaGetSymbolAddress(&df0, g_docf0);
    cudaGetSymbolAddress(&df1, g_docf1);
    cudaGetSymbolAddress(&w1f0, g_w1f0);
    cudaGetSymbolAddress(&w1f1, g_w1f1);
    cudaGetSymbolAddress(&h1f0, g_h1f0);
    cudaGetSymbolAddress(&h1f1, g_h1f1);
    cudaGetSymbolAddress(&w2f0, g_w2f0);
    cudaGetSymbolAddress(&w2f1, g_w2f1);
    cudaGetSymbolAddress(&pP, g_P);

    cudaFuncSetAttribute(nms_kernel, cudaFuncAttributeMaxDynamicSharedMemorySize, NMS_SMEM);

    docfrag<<<(2048 * 384 + 255) / 256, 256>>>(doc);
    wfrag_all<<<(W1E + 512 * NP + 255) / 256, 256>>>(m_w1, m_w2);
    prep_misc<<<287 + 120, 256>>>(doc, head_w, head_b, wpe,
                                  w_w1, w_b1, w_w2, w_b2, w_w3, w_b3,
                                  m_b1, m_b2, m_w3, swe, m_w1);
    // GEMM0: doc @ W1cat   (CTA 128x128)
    frag_gemm<KT0, 0><<<dim3(N0P / 128, 2048 / 128), 256>>>(
        (const uint4*)df0, (const uint4*)df1,
        (const uint4*)w1f0, (const uint4*)w1f1,
        (float*)pP, N0P);
    assemble_h1<<<NC, 256>>>(starts, ends);
    // GEMM2: h1 @ W2 fused with w3 dot
    frag_gemm<KT2, 1><<<dim3(NP / 128, NC / 128), 256>>>(
        (const uint4*)h1f0, (const uint4*)h1f1,
        (const uint4*)w2f0, (const uint4*)w2f1,
        (float*)pP, NP);
    score2<<<(NC + 255) / 256, 256>>>(m_b3, starts, ends, out);
    nms_kernel<<<1, 1024, NMS_SMEM>>>(starts, ends);
    out_top<<<TOPN, 256>>>(out, doc, swe, starts, ends);
}

// round 12
// speedup vs baseline: 1.4380x; 1.2439x over previous
#include <cuda_runtime.h>
#include <cuda_bf16.h>
#include <cstdint>
#include <math.h>

#define NW   2048
#define NC   8192
#define HID  768
#define FEAT 20
#define FFN  1000
#define SD   2324
#define TOPN 819
#define MSW  30
#define NP   1024        // padded FFNN width
#define N0P  3072        // GEMM0 output cols (3 x 1024)
#define KT0  48          // GEMM0 k16 tiles (768/16)
#define KT2  64          // GEMM2 k16 tiles (1024/16)

// ---------------- scratch (device globals) ----------------------------------
__device__ __align__(16) uint32_t g_docf0[2048 * 768 / 2];
__device__ __align__(16) uint32_t g_docf1[2048 * 768 / 2];
__device__ __align__(16) uint32_t g_w1f0[(N0P / 8) * KT0 * 64];
__device__ __align__(16) uint32_t g_w1f1[(N0P / 8) * KT0 * 64];
__device__ __align__(16) uint32_t g_h1f0[(NC / 16) * KT2 * 128];
__device__ __align__(16) uint32_t g_h1f1[(NC / 16) * KT2 * 128];
__device__ __align__(16) uint32_t g_w2f0[(NP / 8) * KT2 * 64];
__device__ __align__(16) uint32_t g_w2f1[(NP / 8) * KT2 * 64];
__device__ __align__(16) float g_P[(size_t)2048 * N0P];     // [P1 | P2 | P3] per word
__device__ __align__(16) float g_wd[MSW * NP];
__device__ __align__(16) float g_b1p[NP];
__device__ __align__(16) float g_b2p[NP];
__device__ __align__(16) float g_w3p[NP];
__device__ float g_part[8][NC];
__device__ float g_wpart[MSW * 4];
__device__ float g_scores[NC];
__device__ float g_head[NW];
__device__ int   g_top[TOPN];

// output offsets (fp32 elements)
#define O1 (NC)
#define O2 (NC + TOPN)
#define O3 (NC + 2*TOPN)
#define O4 (NC + 3*TOPN)
#define O5 (NC + 3*TOPN + TOPN*SD)

// ---------------- helpers ----------------------------------------------------
__device__ __forceinline__ void split2(float v, unsigned short& s0, unsigned short& s1) {
    __nv_bfloat16 b0 = __float2bfloat16(v);
    float r1 = v - __bfloat162float(b0);
    __nv_bfloat16 b1 = __float2bfloat16(r1);
    s0 = __bfloat16_as_ushort(b0);
    s1 = __bfloat16_as_ushort(b1);
}

#define MMA16816(c, a, b) \
    asm volatile("mma.sync.aligned.m16n8k16.row.col.f32.bf16.bf16.f32 " \
        "{%0,%1,%2,%3},{%4,%5,%6,%7},{%8,%9},{%0,%1,%2,%3};" \
        : "+f"((c)[0]), "+f"((c)[1]), "+f"((c)[2]), "+f"((c)[3]) \
        : "r"((a).x), "r"((a).y), "r"((a).z), "r"((a).w), "r"((b).x), "r"((b).y))

// ---------------- fused prep: docfrag | wfrag | head | width | pads | wd -----
#define DOCF_BLKS 3072                       // 2048*384/256
#define W1E (384 * N0P)
#define WF_BLKS 6656                         // (W1E + 512*NP)/256
#define PREP_BASE (DOCF_BLKS + WF_BLKS)      // 9728
// prep section: [0,256) head | [256,376) width | [376] pads | [377,497) wd
#define PREP_BLKS 497

__global__ void prep_all(const float* __restrict__ doc,
                         const float* __restrict__ m_w1, const float* __restrict__ m_w2,
                         const float* __restrict__ hw, const float* __restrict__ hb,
                         const float* __restrict__ wpe,
                         const float* __restrict__ ww1, const float* __restrict__ wb1,
                         const float* __restrict__ ww2, const float* __restrict__ wb2,
                         const float* __restrict__ ww3,
                         const float* __restrict__ m_b1, const float* __restrict__ m_b2,
                         const float* __restrict__ m_w3,
                         const float* __restrict__ swe) {
    int b = blockIdx.x, tid = threadIdx.x;
    if (b < DOCF_BLKS) {
        // ---- doc -> A-fragment bf16 splits ----
        int i = b * 256 + tid;
        int m = i / 384, kp = i % 384;
        int k = kp * 2;
        float v0 = doc[(size_t)m * HID + k];
        float v1 = doc[(size_t)m * HID + k + 1];
        unsigned short a0, a1, b0, b1;
        split2(v0, a0, a1);
        split2(v1, b0, b1);
        int mt = m >> 4, kt = k >> 4, r = m & 15, ck = k & 15;
        int t = ((r & 7) << 2) | ((ck >> 1) & 3);
        int reg = (r >> 3) + 2 * (ck >> 3);
        int idx = (mt * KT0 + kt) * 128 + t * 4 + reg;
        g_docf0[idx] = (uint32_t)a0 | ((uint32_t)b0 << 16);
        g_docf1[idx] = (uint32_t)a1 | ((uint32_t)b1 << 16);
    } else if (b < PREP_BASE) {
        // ---- W1cat + W2 -> B-fragments, kt-paired layout ----
        int i = (b - DOCF_BLKS) * 256 + tid;
        int mode, KP, n, kp;
        if (i < W1E) { mode = 0; KP = 384; }
        else         { mode = 1; KP = 512; i -= W1E; }
        n = i / KP; kp = i % KP;
        int k = kp * 2;
        float v0 = 0.f, v1 = 0.f;
        if (mode == 0) {
            int blk = n >> 10, nn = n & 1023;
            if (nn < FFN) {
                int row = (blk == 0) ? k : (blk == 1) ? 768 + k : 1556 + k;
                v0 = m_w1[(size_t)row * FFN + nn];
                v1 = m_w1[(size_t)(row + 1) * FFN + nn];
            }
        } else {
            if (n < FFN && k < FFN) {
                v0 = m_w2[(size_t)k * FFN + n];
                v1 = (k + 1 < FFN) ? m_w2[(size_t)(k + 1) * FFN + n] : 0.f;
            }
        }
        unsigned short a0, a1, b0, b1;
        split2(v0, a0, a1);
        split2(v1, b0, b1);
        int KTt = mode ? KT2 : KT0;
        int t = ((n & 7) << 2) | ((k >> 1) & 3);
        int idx = ((n >> 3) * (KTt >> 1) + (k >> 5)) * 128
                + t * 4 + (((k >> 4) & 1) << 1) + ((k >> 3) & 1);
        if (mode == 0) {
            g_w1f0[idx] = (uint32_t)a0 | ((uint32_t)b0 << 16);
            g_w1f1[idx] = (uint32_t)a1 | ((uint32_t)b1 << 16);
        } else {
            g_w2f0[idx] = (uint32_t)a0 | ((uint32_t)b0 << 16);
            g_w2f1[idx] = (uint32_t)a1 | ((uint32_t)b1 << 16);
        }
    } else {
        int pb = b - PREP_BASE;
        if (pb < 256) {
            // ---- head scores ----
            int warp = pb * 8 + (tid >> 5);
            int lane = tid & 31;
            const float4* dv = (const float4*)(doc + (size_t)warp * HID);
            const float4* wv = (const float4*)hw;
            float acc = 0.f;
            for (int k = lane; k < HID / 4; k += 32) {
                float4 a = dv[k], w = wv[k];
                acc += a.x*w.x + a.y*w.y + a.z*w.z + a.w*w.w;
            }
            #pragma unroll
            for (int o = 16; o; o >>= 1) acc += __shfl_xor_sync(0xffffffffu, acc, o);
            if (lane == 0) g_head[warp] = acc + hb[0];
        } else if (pb < 376) {
            // ---- width-prior FFNN: row x 4-chunk, 8-deep MLP layer2 ----
            __shared__ float se[FEAT];
            __shared__ float h1[FFN];
            __shared__ float red[256];
            int q = pb - 256;
            int row = q >> 2, chunk = q & 3;
            if (tid < FEAT) se[tid] = wpe[row * FEAT + tid];
            __syncthreads();
            for (int j = tid; j < FFN; j += 256) {
                float acc = wb1[j];
                #pragma unroll
                for (int k = 0; k < FEAT; ++k) acc = fmaf(se[k], ww1[k * FFN + j], acc);
                h1[j] = fmaxf(acc, 0.f);
            }
            __syncthreads();
            float part = 0.f;
            if (tid < 250) {
                int j = chunk * 250 + tid;
                float a[8];
                #pragma unroll
                for (int u = 0; u < 8; ++u) a[u] = 0.f;
                for (int k = 0; k < FFN; k += 8) {
                    #pragma unroll
                    for (int u = 0; u < 8; ++u)
                        a[u] = fmaf(h1[k + u], ww2[(size_t)(k + u) * FFN + j], a[u]);
                }
                float acc = wb2[j] + (((a[0] + a[1]) + (a[2] + a[3]))
                                    + ((a[4] + a[5]) + (a[6] + a[7])));
                part = fmaxf(acc, 0.f) * ww3[j];
            }
            red[tid] = part;
            __syncthreads();
            for (int st = 128; st; st >>= 1) {
                if (tid < st) red[tid] += red[tid + st];
                __syncthreads();
            }
            if (tid == 0) g_wpart[row * 4 + chunk] = red[0];
        } else if (pb < 377) {
            // ---- padded bias / w3 ----
            for (int i = tid; i < NP; i += 256) {
                g_b1p[i] = (i < FFN) ? m_b1[i] : 0.f;
                g_b2p[i] = (i < FFN) ? m_b2[i] : 0.f;
                g_w3p[i] = (i < FFN) ? m_w3[i] : 0.f;
            }
        } else {
            // ---- wd: swe[30x20] @ W1 rows [1536:1556] ----
            int i = (pb - 377) * 256 + tid;
            int w = i / NP, n = i % NP;
            float acc = 0.f;
            if (n < FFN)
                #pragma unroll
                for (int f = 0; f < FEAT; ++f)
                    acc = fmaf(swe[w * FEAT + f], m_w1[(size_t)(1536 + f) * FFN + n], acc);
            g_wd[i] = acc;
        }
    }
}

// ---------------- fragment GEMM: warp tile 64x32, kt-paired B ----------------
// CTA: 128 rows x 128 cols; 8 warps as 2(m) x 4(n); 3 products a0b0,a0b1,a1b0.
template<int KT, int MODE>
__global__ void __launch_bounds__(256, 1)
frag_gemm(const uint4* __restrict__ A0, const uint4* __restrict__ A1,
          const uint4* __restrict__ B0, const uint4* __restrict__ B1,
          float* __restrict__ Cout, int Nstride) {
    int lane = threadIdx.x & 31, wid = threadIdx.x >> 5;
    int wm = wid >> 2, wn = wid & 3;
    int mtb = blockIdx.y * 8 + wm * 4;      // 16-row tiles
    int ntb = blockIdx.x * 16 + wn * 4;     // 8-col tiles
    float c[4][4][4];
    #pragma unroll
    for (int i = 0; i < 4; ++i)
        #pragma unroll
        for (int j = 0; j < 4; ++j)
            #pragma unroll
            for (int q = 0; q < 4; ++q) c[i][j][q] = 0.f;

    for (int p = 0; p < KT / 2; ++p) {
        uint4 bp0[4], bp1[4];
        #pragma unroll
        for (int j = 0; j < 4; ++j) {
            int off = ((ntb + j) * (KT / 2) + p) * 32 + lane;
            bp0[j] = B0[off]; bp1[j] = B1[off];
        }
        #pragma unroll
        for (int q = 0; q < 2; ++q) {
            uint4 a0[4], a1[4];
            #pragma unroll
            for (int i = 0; i < 4; ++i) {
                int off = ((mtb + i) * KT + 2 * p + q) * 32 + lane;
                a0[i] = A0[off]; a1[i] = A1[off];
            }
            #pragma unroll
            for (int i = 0; i < 4; ++i)
                #pragma unroll
                for (int j = 0; j < 4; ++j) {
                    uint2 b0 = q ? make_uint2(bp0[j].z, bp0[j].w)
                                 : make_uint2(bp0[j].x, bp0[j].y);
                    uint2 b1 = q ? make_uint2(bp1[j].z, bp1[j].w)
                                 : make_uint2(bp1[j].x, bp1[j].y);
                    MMA16816(c[i][j], a0[i], b0);
                    MMA16816(c[i][j], a0[i], b1);
                    MMA16816(c[i][j], a1[i], b0);
                }
        }
    }

    int g = lane >> 2, tg = lane & 3;
    if (MODE == 0) {
        #pragma unroll
        for (int i = 0; i < 4; ++i) {
            int m = (mtb + i) * 16 + g;
            #pragma unroll
            for (int j = 0; j < 4; ++j) {
                int n = (ntb + j) * 8 + tg * 2;
                *(float2*)&Cout[(size_t)m * Nstride + n] = make_float2(c[i][j][0], c[i][j][1]);
                *(float2*)&Cout[(size_t)(m + 8) * Nstride + n] = make_float2(c[i][j][2], c[i][j][3]);
            }
        }
    } else {
        __shared__ float sred[4][128];
        #pragma unroll
        for (int i = 0; i < 4; ++i) {
            float r0 = 0.f, r1 = 0.f;
            #pragma unroll
            for (int j = 0; j < 4; ++j) {
                int n = (ntb + j) * 8 + tg * 2;
                float ba = g_b2p[n], bb = g_b2p[n + 1];
                float wa = g_w3p[n], wb = g_w3p[n + 1];
                r0 += fmaxf(c[i][j][0] + ba, 0.f) * wa + fmaxf(c[i][j][1] + bb, 0.f) * wb;
                r1 += fmaxf(c[i][j][2] + ba, 0.f) * wa + fmaxf(c[i][j][3] + bb, 0.f) * wb;
            }
            r0 += __shfl_xor_sync(0xffffffffu, r0, 1);
            r0 += __shfl_xor_sync(0xffffffffu, r0, 2);
            r1 += __shfl_xor_sync(0xffffffffu, r1, 1);
            r1 += __shfl_xor_sync(0xffffffffu, r1, 2);
            if (tg == 0) {
                int lr = wm * 64 + i * 16 + g;
                sred[wn][lr] = r0;
                sred[wn][lr + 8] = r1;
            }
        }
        __syncthreads();
        int tid = threadIdx.x;
        if (tid < 128) {
            float s = sred[0][tid] + sred[1][tid] + sred[2][tid] + sred[3][tid];
            g_part[blockIdx.x][blockIdx.y * 128 + tid] = s;
        }
    }
}

// ---------------- candidate h1 assembly --------------------------------------
__global__ void assemble_h1(const int* __restrict__ starts, const int* __restrict__ ends) {
    int cand = blockIdx.x;
    int s = starts[cand], e = ends[cand], w = e - s;
    __shared__ float attn[32];
    int tid = threadIdx.x;
    if (tid < 32) {
        bool v = (tid <= w);
        float hv = v ? g_head[s + tid] : -INFINITY;
        float m = hv;
        #pragma unroll
        for (int o = 16; o; o >>= 1) m = fmaxf(m, __shfl_xor_sync(0xffffffffu, m, o));
        float ex = v ? expf(hv - m) : 0.f;
        float sum = ex;
        #pragma unroll
        for (int o = 16; o; o >>= 1) sum += __shfl_xor_sync(0xffffffffu, sum, o);
        attn[tid] = ex / sum;
    }
    __syncthreads();

    int n0 = tid * 4;
    float4 p1 = *(const float4*)&g_P[(size_t)s * N0P + n0];
    float4 p2 = *(const float4*)&g_P[(size_t)e * N0P + 1024 + n0];
    float4 wd = *(const float4*)&g_wd[w * NP + n0];
    float4 b1 = *(const float4*)&g_b1p[n0];
    float a0 = p1.x + p2.x + wd.x + b1.x;
    float a1 = p1.y + p2.y + wd.y + b1.y;
    float a2 = p1.z + p2.z + wd.z + b1.z;
    float a3 = p1.w + p2.w + wd.w + b1.w;
    for (int j = 0; j <= w; ++j) {
        float wt = attn[j];
        float4 p3 = *(const float4*)&g_P[(size_t)(s + j) * N0P + 2048 + n0];
        a0 = fmaf(wt, p3.x, a0); a1 = fmaf(wt, p3.y, a1);
        a2 = fmaf(wt, p3.z, a2); a3 = fmaf(wt, p3.w, a3);
    }
    a0 = fmaxf(a0, 0.f); a1 = fmaxf(a1, 0.f);
    a2 = fmaxf(a2, 0.f); a3 = fmaxf(a3, 0.f);

    unsigned short x0[4], x1[4];
    split2(a0, x0[0], x1[0]);
    split2(a1, x0[1], x1[1]);
    split2(a2, x0[2], x1[2]);
    split2(a3, x0[3], x1[3]);

    int mt = cand >> 4, r = cand & 15;
    int kt = n0 >> 4, c4 = n0 & 15;
    int t = ((r & 7) << 2) | ((c4 >> 1) & 3);
    int reg = (r >> 3) + 2 * (c4 >> 3);
    int idx = (mt * KT2 + kt) * 128 + t * 4 + reg;
    g_h1f0[idx]     = (uint32_t)x0[0] | ((uint32_t)x0[1] << 16);
    g_h1f1[idx]     = (uint32_t)x1[0] | ((uint32_t)x1[1] << 16);
    g_h1f0[idx + 4] = (uint32_t)x0[2] | ((uint32_t)x0[3] << 16);
    g_h1f1[idx + 4] = (uint32_t)x1[2] | ((uint32_t)x1[3] << 16);
}

// ---------------- final scores (also writes out[0:NC]) -----------------------
__global__ void score2(const float* __restrict__ b3, const float* __restrict__ wb3,
                       const int* __restrict__ st, const int* __restrict__ en,
                       float* __restrict__ out) {
    __shared__ float wsc[MSW];
    int tid = threadIdx.x;
    if (tid < MSW)
        wsc[tid] = wb3[0] + ((g_wpart[tid*4+0] + g_wpart[tid*4+1])
                           + (g_wpart[tid*4+2] + g_wpart[tid*4+3]));
    __syncthreads();
    int i = blockIdx.x * blockDim.x + tid;
    if (i < NC) {
        float s = b3[0] + wsc[en[i] - st[i]];
        #pragma unroll
        for (int p = 0; p < 8; ++p) s += g_part[p][i];
        g_scores[i] = s;
        out[i] = s;
    }
}

// ---------------- NMS: sort + parallel-validate windowed greedy --------------
#define NMS_SMEM (NC*8 + NC*4*2 + NW*4*2 + 1024*4 + 16 + 1024)

__global__ void __launch_bounds__(1024)
nms_kernel(const int* __restrict__ gstarts, const int* __restrict__ gends) {
    extern __shared__ unsigned char smraw[];
    uint64_t* keys = (uint64_t*)smraw;
    int* sSt = (int*)(keys + NC);
    int* sEn = sSt + NC;
    int* maxEnd = sEn + NC;
    int* minStart = maxEnd + NW;
    int* sel = minStart + NW;
    int* pcount = sel + 1024;
    int* vS   = pcount + 1;
    int* vE   = vS + 32;
    int* vIdx = vE + 32;
    int* vME  = vIdx + 32;
    int* vFlag = vME + 32;
    int tid = threadIdx.x;
    int wi = tid >> 5, lanev = tid & 31;

    for (int i = tid; i < NC; i += 1024) {
        unsigned u = __float_as_uint(g_scores[i]);
        u = (u & 0x80000000u) ? ~u : (u | 0x80000000u);
        keys[i] = ((uint64_t)(~u) << 32) | (unsigned)i;
        sSt[i] = gstarts[i];
        sEn[i] = gends[i];
    }
    for (int i = tid; i < NW; i += 1024) { maxEnd[i] = -1; minStart[i] = NW; }
    if (tid == 0) *pcount = 0;
    __syncthreads();

    for (int k = 2; k <= NC; k <<= 1)
        for (int j = k >> 1; j > 0; j >>= 1) {
            for (int i = tid; i < NC; i += 1024) {
                int ixj = i ^ j;
                if (ixj > i) {
                    bool up = (i & k) == 0;
                    uint64_t a = keys[i], b = keys[ixj];
                    if (up ? (a > b) : (a < b)) { keys[i] = b; keys[ixj] = a; }
                }
            }
            __syncthreads();
        }

    for (int base = 0; base < NC; base += 32) {
        __syncthreads();
        if (*pcount >= TOPN) break;
        {
            int idx = (int)(keys[base + wi] & 0xffffffffu);
            int s = sSt[idx], e = sEn[idx], w = e - s;
            bool bad = false;
            if (lanev > 0 && lanev <= w && maxEnd[s + lanev] > e) bad = true;
            if (lanev < w && minStart[s + lanev] < s) bad = true;
            unsigned badm = __ballot_sync(0xffffffffu, bad);
            if (lanev == 0) {
                int myME = maxEnd[s];
                vS[wi] = s; vE[wi] = e; vIdx[wi] = idx; vME[wi] = myME;
                vFlag[wi] = (badm == 0 && myME != e) ? 1 : 0;
            }
        }
        __syncthreads();
        if (tid < 32) {
            int lane = tid;
            int count = *pcount;
            int s = vS[lane], e = vE[lane], idx = vIdx[lane], myME = vME[lane];
            bool flag = vFlag[lane] != 0;
            unsigned ok = __ballot_sync(0xffffffffu, flag);
            while (ok) {
                int first = __ffs(ok) - 1;
                int s1 = __shfl_sync(0xffffffffu, s, first);
                int e1 = __shfl_sync(0xffffffffu, e, first);
                int idx1 = __shfl_sync(0xffffffffu, idx, first);
                if (lane == 0) {
                    sel[count] = idx1;
                    if (e1 > maxEnd[s1]) maxEnd[s1] = e1;
                    if (s1 < minStart[e1]) minStart[e1] = s1;
                }
                count++;
                if (count == TOPN) break;
                if (lane <= first) flag = false;
                else if (flag) {
                    if (s == s1 && e1 > myME) myME = e1;
                    if (myME == e) flag = false;
                    if ((s < s1 && s1 <= e && e1 > e) ||
                        (s1 < s && e1 >= s && e1 < e)) flag = false;
                }
                ok = __ballot_sync(0xffffffffu, flag);
            }
            if (lane == 0) *pcount = count;
        }
    }
    __syncthreads();
    int count = *pcount;

    {
        uint64_t k;
        if (tid < count) {
            int idx = sel[tid];
            uint64_t pk = (uint64_t)(sSt[idx] * NW + sEn[idx]);
            k = (pk << 24) | ((uint64_t)tid << 14) | (uint64_t)idx;
        } else k = ~0ull;
        keys[tid] = k;
    }
    __syncthreads();
    for (int k = 2; k <= 1024; k <<= 1)
        for (int j = k >> 1; j > 0; j >>= 1) {
            int i = tid, ixj = i ^ j;
            if (ixj > i) {
                bool up = (i & k) == 0;
                uint64_t a = keys[i], b = keys[ixj];
                if (up ? (a > b) : (a < b)) { keys[i] = b; keys[ixj] = a; }
            }
            __syncthreads();
        }
    if (tid < TOPN) {
        uint64_t kt = (tid < count) ? keys[tid] : keys[0];
        g_top[tid] = (int)(kt & 0x3FFFull);
    }
}

// ---------------- outputs: recompute top-span embeddings ---------------------
__global__ void out_top(float* __restrict__ out,
                        const float* __restrict__ doc,
                        const float* __restrict__ swe,
                        const int* __restrict__ starts, const int* __restrict__ ends) {
    int r = blockIdx.x;
    int idx = g_top[r];
    int s = starts[idx], e = ends[idx], w = e - s;
    __shared__ float attn[32];
    int tid = threadIdx.x;
    if (tid < 32) {
        bool v = (tid <= w);
        float hv = v ? g_head[s + tid] : -INFINITY;
        float m = hv;
        #pragma unroll
        for (int o = 16; o; o >>= 1) m = fmaxf(m, __shfl_xor_sync(0xffffffffu, m, o));
        float ex = v ? expf(hv - m) : 0.f;
        float sum = ex;
        #pragma unroll
        for (int o = 16; o; o >>= 1) sum += __shfl_xor_sync(0xffffffffu, sum, o);
        attn[tid] = ex / sum;
    }
    if (tid == 0) {
        out[O1 + r] = (float)idx;
        out[O2 + r] = (float)s;
        out[O3 + r] = (float)e;
        out[O5 + r] = g_scores[idx];
    }
    __syncthreads();
    float* dst = out + O4 + (size_t)r * SD;
    const float4* dv = (const float4*)doc;
    if (tid < HID / 4) {
        int h4 = tid;
        float4 st4 = dv[(size_t)s * 192 + h4];
        float4 en4 = dv[(size_t)e * 192 + h4];
        float4 a = make_float4(0.f, 0.f, 0.f, 0.f);
        for (int j = 0; j <= w; ++j) {
            float wt = attn[j];
            float4 vv = dv[(size_t)(s + j) * 192 + h4];
            a.x = fmaf(wt, vv.x, a.x); a.y = fmaf(wt, vv.y, a.y);
            a.z = fmaf(wt, vv.z, a.z); a.w = fmaf(wt, vv.w, a.w);
        }
        int h = h4 * 4;
        dst[h + 0] = st4.x; dst[h + 1] = st4.y; dst[h + 2] = st4.z; dst[h + 3] = st4.w;
        dst[HID + h + 0] = en4.x; dst[HID + h + 1] = en4.y;
        dst[HID + h + 2] = en4.z; dst[HID + h + 3] = en4.w;
        int ha = 2 * HID + FEAT + h;
        dst[ha + 0] = a.x; dst[ha + 1] = a.y; dst[ha + 2] = a.z; dst[ha + 3] = a.w;
    }
    if (tid >= 224 && tid < 224 + FEAT)
        dst[2 * HID + (tid - 224)] = swe[w * FEAT + (tid - 224)];
}

// ---------------- launch ------------------------------------------------------
extern "C" void kernel_launch(void* const* d_in, const int* in_sizes, int n_in,
                              void* d_out, int out_size) {
    const float* doc    = (const float*)d_in[0];
    const float* swe    = (const float*)d_in[1];
    const float* head_w = (const float*)d_in[2];
    const float* head_b = (const float*)d_in[3];
    const float* m_w1   = (const float*)d_in[4];
    const float* m_b1   = (const float*)d_in[5];
    const float* m_w2   = (const float*)d_in[6];
    const float* m_b2   = (const float*)d_in[7];
    const float* m_w3   = (const float*)d_in[8];
    const float* m_b3   = (const float*)d_in[9];
    const float* wpe    = (const float*)d_in[10];
    const float* w_w1   = (const float*)d_in[11];
    const float* w_b1   = (const float*)d_in[12];
    const float* w_w2   = (const float*)d_in[13];
    const float* w_b2   = (const float*)d_in[14];
    const float* w_w3   = (const float*)d_in[15];
    const float* w_b3   = (const float*)d_in[16];
    const int*   starts = (const int*)d_in[17];
    const int*   ends   = (const int*)d_in[18];
    float* out = (float*)d_out;

    void *df0, *df1, *w1f0, *w1f1, *h1f0, *h1f1, *w2f0, *w2f1, *pP;
    cudaGetSymbolAddress(&df0, g_docf0);
    cudaGetSymbolAddress(&df1, g_docf1);
    cudaGetSymbolAddress(&w1f0, g_w1f0);
    cudaGetSymbolAddress(&w1f1, g_w1f1);
    cudaGetSymbolAddress(&h1f0, g_h1f0);
    cudaGetSymbolAddress(&h1f1, g_h1f1);
    cudaGetSymbolAddress(&w2f0, g_w2f0);
    cudaGetSymbolAddress(&w2f1, g_w2f1);
    cudaGetSymbolAddress(&pP, g_P);

    cudaFuncSetAttribute(nms_kernel, cudaFuncAttributeMaxDynamicSharedMemorySize, NMS_SMEM);

    // 1: all independent prep in one launch
    prep_all<<<PREP_BASE + PREP_BLKS, 256>>>(doc, m_w1, m_w2,
                                             head_w, head_b, wpe,
                                             w_w1, w_b1, w_w2, w_b2, w_w3,
                                             m_b1, m_b2, m_w3, swe);
    // 2: GEMM0 doc @ W1cat
    frag_gemm<KT0, 0><<<dim3(N0P / 128, 2048 / 128), 256>>>(
        (const uint4*)df0, (const uint4*)df1,
        (const uint4*)w1f0, (const uint4*)w1f1,
        (float*)pP, N0P);
    // 3
    assemble_h1<<<NC, 256>>>(starts, ends);
    // 4: GEMM2 h1 @ W2 fused with w3 dot
    frag_gemm<KT2, 1><<<dim3(NP / 128, NC / 128), 256>>>(
        (const uint4*)h1f0, (const uint4*)h1f1,
        (const uint4*)w2f0, (const uint4*)w2f1,
        (float*)pP, NP);
    // 5
    score2<<<(NC + 255) / 256, 256>>>(m_b3, w_b3, starts, ends, out);
    // 6: nms (profiled launch under -s 5 -c 1)
    nms_kernel<<<1, 1024, NMS_SMEM>>>(starts, ends);
    // 7
    out_top<<<TOPN, 256>>>(out, doc, swe, starts, ends);
}

// round 14
// speedup vs baseline: 1.4978x; 1.0416x over previous
#include <cuda_runtime.h>
#include <cuda_bf16.h>
#include <cstdint>
#include <math.h>

#define NW   2048
#define NC   8192
#define HID  768
#define FEAT 20
#define FFN  1000
#define SD   2324
#define TOPN 819
#define MSW  30
#define NP   1024        // padded FFNN width
#define N0P  3072        // GEMM0 output cols (3 x 1024)
#define KT0  48          // GEMM0 k16 tiles (768/16)
#define KT2  64          // GEMM2 k16 tiles (1024/16)

// ---------------- scratch (device globals) ----------------------------------
__device__ __align__(16) uint32_t g_docf0[2048 * 768 / 2];
__device__ __align__(16) uint32_t g_docf1[2048 * 768 / 2];
__device__ __align__(16) uint32_t g_w1f0[(N0P / 8) * KT0 * 64];
__device__ __align__(16) uint32_t g_w1f1[(N0P / 8) * KT0 * 64];
__device__ __align__(16) uint32_t g_h1f0[(NC / 16) * KT2 * 128];
__device__ __align__(16) uint32_t g_h1f1[(NC / 16) * KT2 * 128];
__device__ __align__(16) uint32_t g_w2f0[(NP / 8) * KT2 * 64];
__device__ __align__(16) uint32_t g_w2f1[(NP / 8) * KT2 * 64];
__device__ __align__(16) float g_P[(size_t)2048 * N0P];     // [P1 | P2 | P3] per word
__device__ __align__(16) float g_wd[MSW * NP];
__device__ __align__(16) float g_b1p[NP];
__device__ __align__(16) float g_b2p[NP];
__device__ __align__(16) float g_w3p[NP];
__device__ float g_part[8][NC];
__device__ float g_wpart[MSW * 4];
__device__ float g_scores[NC];
__device__ float g_head[NW];
__device__ int   g_top[TOPN];

// output offsets (fp32 elements)
#define O1 (NC)
#define O2 (NC + TOPN)
#define O3 (NC + 2*TOPN)
#define O4 (NC + 3*TOPN)
#define O5 (NC + 3*TOPN + TOPN*SD)

// ---------------- helpers ----------------------------------------------------
__device__ __forceinline__ void split2(float v, unsigned short& s0, unsigned short& s1) {
    __nv_bfloat16 b0 = __float2bfloat16(v);
    float r1 = v - __bfloat162float(b0);
    __nv_bfloat16 b1 = __float2bfloat16(r1);
    s0 = __bfloat16_as_ushort(b0);
    s1 = __bfloat16_as_ushort(b1);
}

#define MMA16816(c, a, b) \
    asm volatile("mma.sync.aligned.m16n8k16.row.col.f32.bf16.bf16.f32 " \
        "{%0,%1,%2,%3},{%4,%5,%6,%7},{%8,%9},{%0,%1,%2,%3};" \
        : "+f"((c)[0]), "+f"((c)[1]), "+f"((c)[2]), "+f"((c)[3]) \
        : "r"((a).x), "r"((a).y), "r"((a).z), "r"((a).w), "r"((b).x), "r"((b).y))

// ---------------- fused prep: docfrag | wfrag | head | width | pads | wd -----
#define DOCF_BLKS 3072                       // 2048*384/256
#define W1E (384 * N0P)
#define WF_BLKS 6656                         // (W1E + 512*NP)/256
#define PREP_BASE (DOCF_BLKS + WF_BLKS)      // 9728
// prep section: [0,256) head | [256,376) width | [376] pads | [377,497) wd
#define PREP_BLKS 497

__global__ void prep_all(const float* __restrict__ doc,
                         const float* __restrict__ m_w1, const float* __restrict__ m_w2,
                         const float* __restrict__ hw, const float* __restrict__ hb,
                         const float* __restrict__ wpe,
                         const float* __restrict__ ww1, const float* __restrict__ wb1,
                         const float* __restrict__ ww2, const float* __restrict__ wb2,
                         const float* __restrict__ ww3,
                         const float* __restrict__ m_b1, const float* __restrict__ m_b2,
                         const float* __restrict__ m_w3,
                         const float* __restrict__ swe) {
    int b = blockIdx.x, tid = threadIdx.x;
    if (b < DOCF_BLKS) {
        // ---- doc -> A-fragment bf16 splits (coalesced reads) ----
        int i = b * 256 + tid;
        int m = i / 384, kp = i % 384;
        int k = kp * 2;
        float v0 = doc[(size_t)m * HID + k];
        float v1 = doc[(size_t)m * HID + k + 1];
        unsigned short a0, a1, b0, b1;
        split2(v0, a0, a1);
        split2(v1, b0, b1);
        int mt = m >> 4, kt = k >> 4, r = m & 15, ck = k & 15;
        int t = ((r & 7) << 2) | ((ck >> 1) & 3);
        int reg = (r >> 3) + 2 * (ck >> 3);
        int idx = (mt * KT0 + kt) * 128 + t * 4 + reg;
        g_docf0[idx] = (uint32_t)a0 | ((uint32_t)b0 << 16);
        g_docf1[idx] = (uint32_t)a1 | ((uint32_t)b1 << 16);
    } else if (b < PREP_BASE) {
        // ---- W1cat + W2 -> B-fragments, kt-paired; n as FAST index (coalesced) ----
        int i = (b - DOCF_BLKS) * 256 + tid;
        int mode, n, kp;
        if (i < W1E) { mode = 0; kp = i / N0P; n = i % N0P; }
        else         { mode = 1; i -= W1E; kp = i / NP; n = i % NP; }
        int k = kp * 2;
        float v0 = 0.f, v1 = 0.f;
        if (mode == 0) {
            int blk = n >> 10, nn = n & 1023;
            if (nn < FFN) {
                int row = (blk == 0) ? k : (blk == 1) ? 768 + k : 1556 + k;
                v0 = m_w1[(size_t)row * FFN + nn];
                v1 = m_w1[(size_t)(row + 1) * FFN + nn];
            }
        } else {
            if (n < FFN && k < FFN) {
                v0 = m_w2[(size_t)k * FFN + n];
                v1 = (k + 1 < FFN) ? m_w2[(size_t)(k + 1) * FFN + n] : 0.f;
            }
        }
        unsigned short a0, a1, b0, b1;
        split2(v0, a0, a1);
        split2(v1, b0, b1);
        int KTt = mode ? KT2 : KT0;
        int t = ((n & 7) << 2) | ((k >> 1) & 3);
        int idx = ((n >> 3) * (KTt >> 1) + (k >> 5)) * 128
                + t * 4 + (((k >> 4) & 1) << 1) + ((k >> 3) & 1);
        if (mode == 0) {
            g_w1f0[idx] = (uint32_t)a0 | ((uint32_t)b0 << 16);
            g_w1f1[idx] = (uint32_t)a1 | ((uint32_t)b1 << 16);
        } else {
            g_w2f0[idx] = (uint32_t)a0 | ((uint32_t)b0 << 16);
            g_w2f1[idx] = (uint32_t)a1 | ((uint32_t)b1 << 16);
        }
    } else {
        int pb = b - PREP_BASE;
        if (pb < 256) {
            // ---- head scores ----
            int warp = pb * 8 + (tid >> 5);
            int lane = tid & 31;
            const float4* dv = (const float4*)(doc + (size_t)warp * HID);
            const float4* wv = (const float4*)hw;
            float acc = 0.f;
            for (int k = lane; k < HID / 4; k += 32) {
                float4 a = dv[k], w = wv[k];
                acc += a.x*w.x + a.y*w.y + a.z*w.z + a.w*w.w;
            }
            #pragma unroll
            for (int o = 16; o; o >>= 1) acc += __shfl_xor_sync(0xffffffffu, acc, o);
            if (lane == 0) g_head[warp] = acc + hb[0];
        } else if (pb < 376) {
            // ---- width-prior FFNN: row x 4-chunk, 8-deep MLP layer2 ----
            __shared__ float se[FEAT];
            __shared__ float h1[FFN];
            __shared__ float red[256];
            int q = pb - 256;
            int row = q >> 2, chunk = q & 3;
            if (tid < FEAT) se[tid] = wpe[row * FEAT + tid];
            __syncthreads();
            for (int j = tid; j < FFN; j += 256) {
                float acc = wb1[j];
                #pragma unroll
                for (int k = 0; k < FEAT; ++k) acc = fmaf(se[k], ww1[k * FFN + j], acc);
                h1[j] = fmaxf(acc, 0.f);
            }
            __syncthreads();
            float part = 0.f;
            if (tid < 250) {
                int j = chunk * 250 + tid;
                float a[8];
                #pragma unroll
                for (int u = 0; u < 8; ++u) a[u] = 0.f;
                for (int k = 0; k < FFN; k += 8) {
                    #pragma unroll
                    for (int u = 0; u < 8; ++u)
                        a[u] = fmaf(h1[k + u], ww2[(size_t)(k + u) * FFN + j], a[u]);
                }
                float acc = wb2[j] + (((a[0] + a[1]) + (a[2] + a[3]))
                                    + ((a[4] + a[5]) + (a[6] + a[7])));
                part = fmaxf(acc, 0.f) * ww3[j];
            }
            red[tid] = part;
            __syncthreads();
            for (int st = 128; st; st >>= 1) {
                if (tid < st) red[tid] += red[tid + st];
                __syncthreads();
            }
            if (tid == 0) g_wpart[row * 4 + chunk] = red[0];
        } else if (pb < 377) {
            for (int i = tid; i < NP; i += 256) {
                g_b1p[i] = (i < FFN) ? m_b1[i] : 0.f;
                g_b2p[i] = (i < FFN) ? m_b2[i] : 0.f;
                g_w3p[i] = (i < FFN) ? m_w3[i] : 0.f;
            }
        } else {
            int i = (pb - 377) * 256 + tid;
            int w = i / NP, n = i % NP;
            float acc = 0.f;
            if (n < FFN)
                #pragma unroll
                for (int f = 0; f < FEAT; ++f)
                    acc = fmaf(swe[w * FEAT + f], m_w1[(size_t)(1536 + f) * FFN + n], acc);
            g_wd[i] = acc;
        }
    }
}

// ---------------- fragment GEMM: warp tile 64x32, kt-paired B ----------------
template<int KT, int MODE>
__global__ void __launch_bounds__(256, 1)
frag_gemm(const uint4* __restrict__ A0, const uint4* __restrict__ A1,
          const uint4* __restrict__ B0, const uint4* __restrict__ B1,
          float* __restrict__ Cout, int Nstride) {
    int lane = threadIdx.x & 31, wid = threadIdx.x >> 5;
    int wm = wid >> 2, wn = wid & 3;
    int mtb = blockIdx.y * 8 + wm * 4;
    int ntb = blockIdx.x * 16 + wn * 4;
    float c[4][4][4];
    #pragma unroll
    for (int i = 0; i < 4; ++i)
        #pragma unroll
        for (int j = 0; j < 4; ++j)
            #pragma unroll
            for (int q = 0; q < 4; ++q) c[i][j][q] = 0.f;

    for (int p = 0; p < KT / 2; ++p) {
        uint4 bp0[4], bp1[4];
        #pragma unroll
        for (int j = 0; j < 4; ++j) {
            int off = ((ntb + j) * (KT / 2) + p) * 32 + lane;
            bp0[j] = B0[off]; bp1[j] = B1[off];
        }
        #pragma unroll
        for (int q = 0; q < 2; ++q) {
            uint4 a0[4], a1[4];
            #pragma unroll
            for (int i = 0; i < 4; ++i) {
                int off = ((mtb + i) * KT + 2 * p + q) * 32 + lane;
                a0[i] = A0[off]; a1[i] = A1[off];
            }
            #pragma unroll
            for (int i = 0; i < 4; ++i)
                #pragma unroll
                for (int j = 0; j < 4; ++j) {
                    uint2 b0 = q ? make_uint2(bp0[j].z, bp0[j].w)
                                 : make_uint2(bp0[j].x, bp0[j].y);
                    uint2 b1 = q ? make_uint2(bp1[j].z, bp1[j].w)
                                 : make_uint2(bp1[j].x, bp1[j].y);
                    MMA16816(c[i][j], a0[i], b0);
                    MMA16816(c[i][j], a0[i], b1);
                    MMA16816(c[i][j], a1[i], b0);
                }
        }
    }

    int g = lane >> 2, tg = lane & 3;
    if (MODE == 0) {
        #pragma unroll
        for (int i = 0; i < 4; ++i) {
            int m = (mtb + i) * 16 + g;
            #pragma unroll
            for (int j = 0; j < 4; ++j) {
                int n = (ntb + j) * 8 + tg * 2;
                *(float2*)&Cout[(size_t)m * Nstride + n] = make_float2(c[i][j][0], c[i][j][1]);
                *(float2*)&Cout[(size_t)(m + 8) * Nstride + n] = make_float2(c[i][j][2], c[i][j][3]);
            }
        }
    } else {
        __shared__ float sred[4][128];
        #pragma unroll
        for (int i = 0; i < 4; ++i) {
            float r0 = 0.f, r1 = 0.f;
            #pragma unroll
            for (int j = 0; j < 4; ++j) {
                int n = (ntb + j) * 8 + tg * 2;
                float ba = g_b2p[n], bb = g_b2p[n + 1];
                float wa = g_w3p[n], wb = g_w3p[n + 1];
                r0 += fmaxf(c[i][j][0] + ba, 0.f) * wa + fmaxf(c[i][j][1] + bb, 0.f) * wb;
                r1 += fmaxf(c[i][j][2] + ba, 0.f) * wa + fmaxf(c[i][j][3] + bb, 0.f) * wb;
            }
            r0 += __shfl_xor_sync(0xffffffffu, r0, 1);
            r0 += __shfl_xor_sync(0xffffffffu, r0, 2);
            r1 += __shfl_xor_sync(0xffffffffu, r1, 1);
            r1 += __shfl_xor_sync(0xffffffffu, r1, 2);
            if (tg == 0) {
                int lr = wm * 64 + i * 16 + g;
                sred[wn][lr] = r0;
                sred[wn][lr + 8] = r1;
            }
        }
        __syncthreads();
        int tid = threadIdx.x;
        if (tid < 128) {
            float s = sred[0][tid] + sred[1][tid] + sred[2][tid] + sred[3][tid];
            g_part[blockIdx.x][blockIdx.y * 128 + tid] = s;
        }
    }
}

// ---------------- candidate h1 assembly --------------------------------------
__global__ void assemble_h1(const int* __restrict__ starts, const int* __restrict__ ends) {
    int cand = blockIdx.x;
    int s = starts[cand], e = ends[cand], w = e - s;
    __shared__ float attn[32];
    int tid = threadIdx.x;
    if (tid < 32) {
        bool v = (tid <= w);
        float hv = v ? g_head[s + tid] : -INFINITY;
        float m = hv;
        #pragma unroll
        for (int o = 16; o; o >>= 1) m = fmaxf(m, __shfl_xor_sync(0xffffffffu, m, o));
        float ex = v ? expf(hv - m) : 0.f;
        float sum = ex;
        #pragma unroll
        for (int o = 16; o; o >>= 1) sum += __shfl_xor_sync(0xffffffffu, sum, o);
        attn[tid] = ex / sum;
    }
    __syncthreads();

    int n0 = tid * 4;
    float4 p1 = *(const float4*)&g_P[(size_t)s * N0P + n0];
    float4 p2 = *(const float4*)&g_P[(size_t)e * N0P + 1024 + n0];
    float4 wd = *(const float4*)&g_wd[w * NP + n0];
    float4 b1 = *(const float4*)&g_b1p[n0];
    float a0 = p1.x + p2.x + wd.x + b1.x;
    float a1 = p1.y + p2.y + wd.y + b1.y;
    float a2 = p1.z + p2.z + wd.z + b1.z;
    float a3 = p1.w + p2.w + wd.w + b1.w;
    for (int j = 0; j <= w; ++j) {
        float wt = attn[j];
        float4 p3 = *(const float4*)&g_P[(size_t)(s + j) * N0P + 2048 + n0];
        a0 = fmaf(wt, p3.x, a0); a1 = fmaf(wt, p3.y, a1);
        a2 = fmaf(wt, p3.z, a2); a3 = fmaf(wt, p3.w, a3);
    }
    a0 = fmaxf(a0, 0.f); a1 = fmaxf(a1, 0.f);
    a2 = fmaxf(a2, 0.f); a3 = fmaxf(a3, 0.f);

    unsigned short x0[4], x1[4];
    split2(a0, x0[0], x1[0]);
    split2(a1, x0[1], x1[1]);
    split2(a2, x0[2], x1[2]);
    split2(a3, x0[3], x1[3]);

    int mt = cand >> 4, r = cand & 15;
    int kt = n0 >> 4, c4 = n0 & 15;
    int t = ((r & 7) << 2) | ((c4 >> 1) & 3);
    int reg = (r >> 3) + 2 * (c4 >> 3);
    int idx = (mt * KT2 + kt) * 128 + t * 4 + reg;
    g_h1f0[idx]     = (uint32_t)x0[0] | ((uint32_t)x0[1] << 16);
    g_h1f1[idx]     = (uint32_t)x1[0] | ((uint32_t)x1[1] << 16);
    g_h1f0[idx + 4] = (uint32_t)x0[2] | ((uint32_t)x0[3] << 16);
    g_h1f1[idx + 4] = (uint32_t)x1[2] | ((uint32_t)x1[3] << 16);
}

// ---------------- final scores (also writes out[0:NC]) -----------------------
__global__ void score2(const float* __restrict__ b3, const float* __restrict__ wb3,
                       const int* __restrict__ st, const int* __restrict__ en,
                       float* __restrict__ out) {
    __shared__ float wsc[MSW];
    int tid = threadIdx.x;
    if (tid < MSW)
        wsc[tid] = wb3[0] + ((g_wpart[tid*4+0] + g_wpart[tid*4+1])
                           + (g_wpart[tid*4+2] + g_wpart[tid*4+3]));
    __syncthreads();
    int i = blockIdx.x * blockDim.x + tid;
    if (i < NC) {
        float s = b3[0] + wsc[en[i] - st[i]];
        #pragma unroll
        for (int p = 0; p < 8; ++p) s += g_part[p][i];
        g_scores[i] = s;
        out[i] = s;
    }
}

// ---------------- NMS: shfl/register bitonic + parallel greedy ---------------
#define NMS_SMEM (NC*8 + NC*4*2 + NW*4*2 + 1024*4 + 16 + 1024)

__device__ __forceinline__ uint64_t shfl64x(uint64_t v, int d) {
    uint32_t lo = (uint32_t)v, hi = (uint32_t)(v >> 32);
    lo = __shfl_xor_sync(0xffffffffu, lo, d);
    hi = __shfl_xor_sync(0xffffffffu, hi, d);
    return ((uint64_t)hi << 32) | lo;
}

// register/shfl stages of bitonic pass k for j = min(k/2,128) .. 1
__device__ __forceinline__ void bitonic_window(uint64_t e[8], int tid, int k) {
    int base = tid * 8;
    // shfl stages j = 8..128 (partner thread = tid ^ (j/8), same warp)
    for (int j = (k >> 1) > 128 ? 128 : (k >> 1); j >= 8; j >>= 1) {
        int d = j >> 3;
        bool lower = ((tid & d) == 0);
        bool up = ((base & k) == 0);      // k > j >= 8 -> bit of k in tid part
        bool takeMin = (up == lower);
        #pragma unroll
        for (int u = 0; u < 8; ++u) {
            uint64_t other = shfl64x(e[u], d);
            bool keepMin = (e[u] < other);
            e[u] = (takeMin == keepMin) ? e[u] : other;
        }
    }
    // in-register stages j = 4,2,1
    for (int j = (k >> 1) > 4 ? 4 : (k >> 1); j >= 1; j >>= 1) {
        #pragma unroll
        for (int u = 0; u < 8; ++u) {
            if (!(u & j)) {
                bool up = (((base + u) & k) == 0);
                uint64_t a = e[u], b = e[u + j];
                uint64_t lo = a < b ? a : b, hi = a < b ? b : a;
                e[u]     = up ? lo : hi;
                e[u + j] = up ? hi : lo;
            }
        }
    }
}

__global__ void __launch_bounds__(1024)
nms_kernel(const int* __restrict__ gstarts, const int* __restrict__ gends) {
    extern __shared__ unsigned char smraw[];
    uint64_t* keys = (uint64_t*)smraw;
    int* sSt = (int*)(keys + NC);
    int* sEn = sSt + NC;
    int* maxEnd = sEn + NC;
    int* minStart = maxEnd + NW;
    int* sel = minStart + NW;
    int* pcount = sel + 1024;
    int* vS   = pcount + 1;
    int* vE   = vS + 32;
    int* vIdx = vE + 32;
    int* vME  = vIdx + 32;
    int* vFlag = vME + 32;
    int tid = threadIdx.x;
    int wi = tid >> 5, lanev = tid & 31;

    for (int i = tid; i < NC; i += 1024) {
        unsigned u = __float_as_uint(g_scores[i]);
        u = (u & 0x80000000u) ? ~u : (u | 0x80000000u);
        keys[i] = ((uint64_t)(~u) << 32) | (unsigned)i;
        sSt[i] = gstarts[i];
        sEn[i] = gends[i];
    }
    for (int i = tid; i < NW; i += 1024) { maxEnd[i] = -1; minStart[i] = NW; }
    if (tid == 0) *pcount = 0;
    __syncthreads();

    // ---- bitonic sort, shfl/register-accelerated ----
    {   // k = 2..256 entirely in registers/shfl: one load + one store
        uint64_t e[8];
        #pragma unroll
        for (int u = 0; u < 8; ++u) e[u] = keys[tid * 8 + u];
        for (int k = 2; k <= 256; k <<= 1) bitonic_window(e, tid, k);
        #pragma unroll
        for (int u = 0; u < 8; ++u) keys[tid * 8 + u] = e[u];
    }
    __syncthreads();
    for (int k = 512; k <= NC; k <<= 1) {
        // smem passes for j >= 256 (cross-warp partners)
        for (int j = k >> 1; j >= 256; j >>= 1) {
            for (int i = tid; i < NC; i += 1024) {
                int ixj = i ^ j;
                if (ixj > i) {
                    bool up = (i & k) == 0;
                    uint64_t a = keys[i], b = keys[ixj];
                    if (up ? (a > b) : (a < b)) { keys[i] = b; keys[ixj] = a; }
                }
            }
            __syncthreads();
        }
        // j = 128..1 in one register window
        uint64_t e[8];
        #pragma unroll
        for (int u = 0; u < 8; ++u) e[u] = keys[tid * 8 + u];
        bitonic_window(e, tid, k);
        #pragma unroll
        for (int u = 0; u < 8; ++u) keys[tid * 8 + u] = e[u];
        __syncthreads();
    }

    // ---- windowed greedy: parallel validate + exact sequential commit ----
    for (int base = 0; base < NC; base += 32) {
        __syncthreads();
        if (*pcount >= TOPN) break;
        {
            int idx = (int)(keys[base + wi] & 0xffffffffu);
            int s = sSt[idx], e = sEn[idx], w = e - s;
            bool bad = false;
            if (lanev > 0 && lanev <= w && maxEnd[s + lanev] > e) bad = true;
            if (lanev < w && minStart[s + lanev] < s) bad = true;
            unsigned badm = __ballot_sync(0xffffffffu, bad);
            if (lanev == 0) {
                int myME = maxEnd[s];
                vS[wi] = s; vE[wi] = e; vIdx[wi] = idx; vME[wi] = myME;
                vFlag[wi] = (badm == 0 && myME != e) ? 1 : 0;
            }
        }
        __syncthreads();
        if (tid < 32) {
            int lane = tid;
            int count = *pcount;
            int s = vS[lane], e = vE[lane], idx = vIdx[lane], myME = vME[lane];
            bool flag = vFlag[lane] != 0;
            unsigned ok = __ballot_sync(0xffffffffu, flag);
            while (ok) {
                int first = __ffs(ok) - 1;
                int s1 = __shfl_sync(0xffffffffu, s, first);
                int e1 = __shfl_sync(0xffffffffu, e, first);
                int idx1 = __shfl_sync(0xffffffffu, idx, first);
                if (lane == 0) {
                    sel[count] = idx1;
                    if (e1 > maxEnd[s1]) maxEnd[s1] = e1;
                    if (s1 < minStart[e1]) minStart[e1] = s1;
                }
                count++;
                if (count == TOPN) break;
                if (lane <= first) flag = false;
                else if (flag) {
                    if (s == s1 && e1 > myME) myME = e1;
                    if (myME == e) flag = false;
                    if ((s < s1 && s1 <= e && e1 > e) ||
                        (s1 < s && e1 >= s && e1 < e)) flag = false;
                }
                ok = __ballot_sync(0xffffffffu, flag);
            }
            if (lane == 0) *pcount = count;
        }
    }
    __syncthreads();
    int count = *pcount;

    {
        uint64_t k;
        if (tid < count) {
            int idx = sel[tid];
            uint64_t pk = (uint64_t)(sSt[idx] * NW + sEn[idx]);
            k = (pk << 24) | ((uint64_t)tid << 14) | (uint64_t)idx;
        } else k = ~0ull;
        keys[tid] = k;
    }
    __syncthreads();
    for (int k = 2; k <= 1024; k <<= 1)
        for (int j = k >> 1; j > 0; j >>= 1) {
            int i = tid, ixj = i ^ j;
            if (ixj > i) {
                bool up = (i & k) == 0;
                uint64_t a = keys[i], b = keys[ixj];
                if (up ? (a > b) : (a < b)) { keys[i] = b; keys[ixj] = a; }
            }
            __syncthreads();
        }
    if (tid < TOPN) {
        uint64_t kt = (tid < count) ? keys[tid] : keys[0];
        g_top[tid] = (int)(kt & 0x3FFFull);
    }
}

// ---------------- outputs: recompute top-span embeddings ---------------------
__global__ void out_top(float* __restrict__ out,
                        const float* __restrict__ doc,
                        const float* __restrict__ swe,
                        const int* __restrict__ starts, const int* __restrict__ ends) {
    int r = blockIdx.x;
    int idx = g_top[r];
    int s = starts[idx], e = ends[idx], w = e - s;
    __shared__ float attn[32];
    int tid = threadIdx.x;
    if (tid < 32) {
        bool v = (tid <= w);
        float hv = v ? g_head[s + tid] : -INFINITY;
        float m = hv;
        #pragma unroll
        for (int o = 16; o; o >>= 1) m = fmaxf(m, __shfl_xor_sync(0xffffffffu, m, o));
        float ex = v ? expf(hv - m) : 0.f;
        float sum = ex;
        #pragma unroll
        for (int o = 16; o; o >>= 1) sum += __shfl_xor_sync(0xffffffffu, sum, o);
        attn[tid] = ex / sum;
    }
    if (tid == 0) {
        out[O1 + r] = (float)idx;
        out[O2 + r] = (float)s;
        out[O3 + r] = (float)e;
        out[O5 + r] = g_scores[idx];
    }
    __syncthreads();
    float* dst = out + O4 + (size_t)r * SD;
    const float4* dv = (const float4*)doc;
    if (tid < HID / 4) {
        int h4 = tid;
        float4 st4 = dv[(size_t)s * 192 + h4];
        float4 en4 = dv[(size_t)e * 192 + h4];
        float4 a = make_float4(0.f, 0.f, 0.f, 0.f);
        for (int j = 0; j <= w; ++j) {
            float wt = attn[j];
            float4 vv = dv[(size_t)(s + j) * 192 + h4];
            a.x = fmaf(wt, vv.x, a.x); a.y = fmaf(wt, vv.y, a.y);
            a.z = fmaf(wt, vv.z, a.z); a.w = fmaf(wt, vv.w, a.w);
        }
        int h = h4 * 4;
        dst[h + 0] = st4.x; dst[h + 1] = st4.y; dst[h + 2] = st4.z; dst[h + 3] = st4.w;
        dst[HID + h + 0] = en4.x; dst[HID + h + 1] = en4.y;
        dst[HID + h + 2] = en4.z; dst[HID + h + 3] = en4.w;
        int ha = 2 * HID + FEAT + h;
        dst[ha + 0] = a.x; dst[ha + 1] = a.y; dst[ha + 2] = a.z; dst[ha + 3] = a.w;
    }
    if (tid >= 224 && tid < 224 + FEAT)
        dst[2 * HID + (tid - 224)] = swe[w * FEAT + (tid - 224)];
}

// ---------------- launch ------------------------------------------------------
extern "C" void kernel_launch(void* const* d_in, const int* in_sizes, int n_in,
                              void* d_out, int out_size) {
    const float* doc    = (const float*)d_in[0];
    const float* swe    = (const float*)d_in[1];
    const float* head_w = (const float*)d_in[2];
    const float* head_b = (const float*)d_in[3];
    const float* m_w1   = (const float*)d_in[4];
    const float* m_b1   = (const float*)d_in[5];
    const float* m_w2   = (const float*)d_in[6];
    const float* m_b2   = (const float*)d_in[7];
    const float* m_w3   = (const float*)d_in[8];
    const float* m_b3   = (const float*)d_in[9];
    const float* wpe    = (const float*)d_in[10];
    const float* w_w1   = (const float*)d_in[11];
    const float* w_b1   = (const float*)d_in[12];
    const float* w_w2   = (const float*)d_in[13];
    const float* w_b2   = (const float*)d_in[14];
    const float* w_w3   = (const float*)d_in[15];
    const float* w_b3   = (const float*)d_in[16];
    const int*   starts = (const int*)d_in[17];
    const int*   ends   = (const int*)d_in[18];
    float* out = (float*)d_out;

    void *df0, *df1, *w1f0, *w1f1, *h1f0, *h1f1, *w2f0, *w2f1, *pP;
    cudaGetSymbolAddress(&df0, g_docf0);
    cudaGetSymbolAddress(&df1, g_docf1);
    cudaGetSymbolAddress(&w1f0, g_w1f0);
    cudaGetSymbolAddress(&w1f1, g_w1f1);
    cudaGetSymbolAddress(&h1f0, g_h1f0);
    cudaGetSymbolAddress(&h1f1, g_h1f1);
    cudaGetSymbolAddress(&w2f0, g_w2f0);
    cudaGetSymbolAddress(&w2f1, g_w2f1);
    cudaGetSymbolAddress(&pP, g_P);

    cudaFuncSetAttribute(nms_kernel, cudaFuncAttributeMaxDynamicSharedMemorySize, NMS_SMEM);

    prep_all<<<PREP_BASE + PREP_BLKS, 256>>>(doc, m_w1, m_w2,
                                             head_w, head_b, wpe,
                                             w_w1, w_b1, w_w2, w_b2, w_w3,
                                             m_b1, m_b2, m_w3, swe);
    frag_gemm<KT0, 0><<<dim3(N0P / 128, 2048 / 128), 256>>>(
        (const uint4*)df0, (const uint4*)df1,
        (const uint4*)w1f0, (const uint4*)w1f1,
        (float*)pP, N0P);
    assemble_h1<<<NC, 256>>>(starts, ends);
    frag_gemm<KT2, 1><<<dim3(NP / 128, NC / 128), 256>>>(
        (const uint4*)h1f0, (const uint4*)h1f1,
        (const uint4*)w2f0, (const uint4*)w2f1,
        (float*)pP, NP);
    score2<<<(NC + 255) / 256, 256>>>(m_b3, w_b3, starts, ends, out);
    nms_kernel<<<1, 1024, NMS_SMEM>>>(starts, ends);
    out_top<<<TOPN, 256>>>(out, doc, swe, starts, ends);
}